// round 14
// baseline (speedup 1.0000x reference)
#include <cuda_runtime.h>
#include <cuda_fp16.h>

#define N_NODES 100000
#define E_EDGES 1600000
#define IN_DIM 32
#define HID 64
#define NHEADS 2
#define F1 128   // NHEADS*HID
#define OUTC 64
#define LOG2E 1.4426950408889634f

#define CSR_BLOCKS 512
#define CSR_THREADS 256

// ---------------- scratch (device globals; no allocation allowed) ------------
__device__ __align__(16) __half g_h1h [(size_t)(N_NODES + 1) * F1];
__device__ __align__(16) __half g_hlnh[(size_t)N_NODES * F1];
__device__ __align__(16) __half g_h2h [(size_t)(N_NODES + 1) * OUTC];
__device__ __align__(16) float g_as1[(N_NODES + 1) * NHEADS];
__device__ __align__(16) float g_ad1[(N_NODES + 1) * NHEADS];
__device__ float g_as2[N_NODES + 1];
__device__ float g_ad2[N_NODES + 1];
__device__ int   g_deg[N_NODES];          // ZERO at kernel_launch entry (BSS init + tail-zeroed by k_gather2)
__device__ int   g_off[N_NODES + 1];
__device__ int   g_cur[N_NODES];
__device__ __align__(16) int g_csr[E_EDGES + 3 * N_NODES + 8];
__device__ int   g_bsum[CSR_BLOCKS];
__device__ int   g_bscan[CSR_BLOCKS];
__device__ __align__(16) float g_was2[F1];
__device__ __align__(16) float g_wad2[F1];
__device__ int   g_bar_count;
__device__ int   g_bar_gen;

__device__ __forceinline__ float lrelu(float v) { return v > 0.f ? v : 0.2f * v; }

// ---- packed fp32x2 helpers ----------------------------------------------------
__device__ __forceinline__ unsigned long long packdup(float a) {
    unsigned long long r;
    asm("mov.b64 %0, {%1, %1};" : "=l"(r) : "f"(a));
    return r;
}
__device__ __forceinline__ void ffma2(unsigned long long& acc,
                                      unsigned long long a, unsigned long long b) {
    asm("fma.rn.f32x2 %0, %1, %2, %0;" : "+l"(acc) : "l"(a), "l"(b));
}
__device__ __forceinline__ float lo32(unsigned long long v) {
    return __uint_as_float((unsigned)(v & 0xffffffffull));
}
__device__ __forceinline__ float hi32(unsigned long long v) {
    return __uint_as_float((unsigned)(v >> 32));
}
__device__ __forceinline__ float2 h2f2(unsigned h) {
    return __half22float2(reinterpret_cast<__half2&>(h));
}

// ---- software grid barrier (csr blocks only) -----------------------------------
__device__ __forceinline__ void gsync() {
    __syncthreads();
    __threadfence();
    if (threadIdx.x == 0) {
        int gen = *(volatile int*)&g_bar_gen;
        if (atomicAdd(&g_bar_count, 1) == CSR_BLOCKS - 1) {
            g_bar_count = 0;
            __threadfence();
            *(volatile int*)&g_bar_gen = gen + 1;
        } else {
            while (*(volatile int*)&g_bar_gen == gen) { }
        }
        __threadfence();
    }
    __syncthreads();
}

// ===== mega kernel: blocks [0,512) build CSR; blocks [512,...) do fold2+proj1 ===
// PRECONDITION: g_deg == 0 (BSS at load; re-zeroed by k_gather2 tail each call)
__global__ void __launch_bounds__(256, 4)
k_mega(const int* __restrict__ src, const int* __restrict__ dst, int E, int n,
       const float* __restrict__ x, const float* __restrict__ W1,
       const float* __restrict__ attS, const float* __restrict__ attD,
       const float* __restrict__ W2,
       const float* __restrict__ as2v, const float* __restrict__ ad2v) {
    __shared__ __align__(16) float Ws[IN_DIM * F1];      // proj: weights | csr: wsum alias
    __shared__ __align__(16) float xsT[IN_DIM][36];
    int t = threadIdx.x;

    if (blockIdx.x < CSR_BLOCKS) {
        // -------------------- CSR path --------------------
        int* wsum = (int*)xsT;
        const int T = CSR_BLOCKS * CSR_THREADS;
        int gt = blockIdx.x * CSR_THREADS + t;
        int lane = t & 31, w = t >> 5;

        // P1: count degrees (2 int4 chunks in flight)
        int E4 = E >> 2;
        int i = gt;
        for (; i + T < E4; i += 2 * T) {
            int4 a = ((const int4*)dst)[i];
            int4 b = ((const int4*)dst)[i + T];
            atomicAdd(&g_deg[a.x], 1); atomicAdd(&g_deg[a.y], 1);
            atomicAdd(&g_deg[a.z], 1); atomicAdd(&g_deg[a.w], 1);
            atomicAdd(&g_deg[b.x], 1); atomicAdd(&g_deg[b.y], 1);
            atomicAdd(&g_deg[b.z], 1); atomicAdd(&g_deg[b.w], 1);
        }
        if (i < E4) {
            int4 a = ((const int4*)dst)[i];
            atomicAdd(&g_deg[a.x], 1); atomicAdd(&g_deg[a.y], 1);
            atomicAdd(&g_deg[a.z], 1); atomicAdd(&g_deg[a.w], 1);
        }
        for (int e = E4 * 4 + gt; e < E; e += T) atomicAdd(&g_deg[dst[e]], 1);
        gsync();
        // P2: per-thread chunk sum (padded to 4) + block scan
        int C = (n + T - 1) / T;
        int b0 = gt * C;
        int s = 0;
        for (int j = 0; j < C; ++j) {
            int idx = b0 + j;
            if (idx < n) s += (g_deg[idx] + 3) & ~3;
        }
        int incl = s;
        #pragma unroll
        for (int o = 1; o < 32; o <<= 1) {
            int xv = __shfl_up_sync(0xffffffffu, incl, o);
            if (lane >= o) incl += xv;
        }
        if (lane == 31) wsum[w] = incl;
        __syncthreads();
        if (t < 8) {
            int xv = wsum[t];
            #pragma unroll
            for (int o = 1; o < 8; o <<= 1) {
                int y = __shfl_up_sync(0xffu, xv, o);
                if (t >= o) xv += y;
            }
            wsum[t] = xv;
        }
        __syncthreads();
        int excl = incl - s + (w > 0 ? wsum[w - 1] : 0);
        if (t == CSR_THREADS - 1) g_bsum[blockIdx.x] = excl + s;
        gsync();
        // P3: block 0 scans block totals
        if (blockIdx.x == 0) {
            int a0 = g_bsum[2 * t], a1 = g_bsum[2 * t + 1];
            int ss = a0 + a1;
            int in2 = ss;
            #pragma unroll
            for (int o = 1; o < 32; o <<= 1) {
                int xv = __shfl_up_sync(0xffffffffu, in2, o);
                if (lane >= o) in2 += xv;
            }
            if (lane == 31) wsum[w] = in2;
            __syncthreads();
            if (t < 8) {
                int xv = wsum[t];
                #pragma unroll
                for (int o = 1; o < 8; o <<= 1) {
                    int y = __shfl_up_sync(0xffu, xv, o);
                    if (t >= o) xv += y;
                }
                wsum[t] = xv;
            }
            __syncthreads();
            int ex2 = in2 - ss + (w > 0 ? wsum[w - 1] : 0);
            g_bscan[2 * t]     = ex2;
            g_bscan[2 * t + 1] = ex2 + a0;
        }
        gsync();
        // P4: write offsets (padded), fill pad slots with dummy node n
        int off = excl + g_bscan[blockIdx.x];
        for (int j = 0; j < C; ++j) {
            int idx = b0 + j;
            if (idx < n) {
                int d = g_deg[idx];
                int p = (d + 3) & ~3;
                g_off[idx] = off;
                g_cur[idx] = off;
                for (int k = d; k < p; ++k) g_csr[off + k] = n;  // dummy
                if (idx == n - 1) g_off[n] = off + p;
                off += p;
            }
        }
        gsync();
        // P5: scatter (2 chunks in flight)
        i = gt;
        for (; i + T < E4; i += 2 * T) {
            int4 sa = ((const int4*)src)[i];
            int4 da = ((const int4*)dst)[i];
            int4 sb = ((const int4*)src)[i + T];
            int4 db = ((const int4*)dst)[i + T];
            g_csr[atomicAdd(&g_cur[da.x], 1)] = sa.x;
            g_csr[atomicAdd(&g_cur[da.y], 1)] = sa.y;
            g_csr[atomicAdd(&g_cur[da.z], 1)] = sa.z;
            g_csr[atomicAdd(&g_cur[da.w], 1)] = sa.w;
            g_csr[atomicAdd(&g_cur[db.x], 1)] = sb.x;
            g_csr[atomicAdd(&g_cur[db.y], 1)] = sb.y;
            g_csr[atomicAdd(&g_cur[db.z], 1)] = sb.z;
            g_csr[atomicAdd(&g_cur[db.w], 1)] = sb.w;
        }
        if (i < E4) {
            int4 sa = ((const int4*)src)[i];
            int4 da = ((const int4*)dst)[i];
            g_csr[atomicAdd(&g_cur[da.x], 1)] = sa.x;
            g_csr[atomicAdd(&g_cur[da.y], 1)] = sa.y;
            g_csr[atomicAdd(&g_cur[da.z], 1)] = sa.z;
            g_csr[atomicAdd(&g_cur[da.w], 1)] = sa.w;
        }
        for (int e = E4 * 4 + gt; e < E; e += T) {
            g_csr[atomicAdd(&g_cur[dst[e]], 1)] = src[e];
        }
        return;
    }

    // -------------------- fold2 + proj1 path --------------------
    int pb = blockIdx.x - CSR_BLOCKS;
    if (pb == 0) {
        if (t < F1) {
            float s = 0.f, d = 0.f;
            for (int c = 0; c < OUTC; ++c) {
                float wv = W2[t * OUTC + c];
                s += wv * as2v[c];
                d += wv * ad2v[c];
            }
            g_was2[t] = s;
            g_wad2[t] = d;
            g_h1h[(size_t)n * F1 + t] = __float2half(0.f);
        }
        if (t < 2) { g_as1[2 * n + t] = -1e30f; g_ad1[2 * n + t] = 0.f; }
        if (t == 0) { g_as2[n] = -1e30f; g_ad2[n] = 0.f; }
        if (t < OUTC) g_h2h[(size_t)n * OUTC + t] = __float2half(0.f);
    }
    for (int i = t; i < IN_DIM * F1; i += 256) Ws[i] = W1[i];
    int base = pb * 32;
    #pragma unroll
    for (int i = 0; i < 4; ++i) {
        int idx = t + i * 256;
        int node = idx >> 5, k = idx & 31;
        int nn = base + node;
        xsT[k][node] = (nn < n) ? x[(size_t)nn * IN_DIM + k] : 0.f;
    }
    __syncthreads();
    int tx = t & 31;
    int ty = t >> 5;
    unsigned long long acc[4][2] = {};
    #pragma unroll
    for (int k = 0; k < IN_DIM; ++k) {
        ulonglong2 w = *(const ulonglong2*)&Ws[k * F1 + tx * 4];
        float4 xv = *(const float4*)&xsT[k][ty * 4];
        unsigned long long xp0 = packdup(xv.x), xp1 = packdup(xv.y);
        unsigned long long xp2 = packdup(xv.z), xp3 = packdup(xv.w);
        ffma2(acc[0][0], w.x, xp0); ffma2(acc[0][1], w.y, xp0);
        ffma2(acc[1][0], w.x, xp1); ffma2(acc[1][1], w.y, xp1);
        ffma2(acc[2][0], w.x, xp2); ffma2(acc[2][1], w.y, xp2);
        ffma2(acc[3][0], w.x, xp3); ffma2(acc[3][1], w.y, xp3);
    }
    float4 av = __ldg((const float4*)&attS[tx * 4]);
    float4 dvv = __ldg((const float4*)&attD[tx * 4]);
    #pragma unroll
    for (int i = 0; i < 4; ++i) {
        int nn = base + ty * 4 + i;
        float f0 = lo32(acc[i][0]), f1 = hi32(acc[i][0]);
        float f2 = lo32(acc[i][1]), f3 = hi32(acc[i][1]);
        if (nn < n) {
            __half2 p01 = __floats2half2_rn(f0, f1);
            __half2 p23 = __floats2half2_rn(f2, f3);
            uint2 u;
            u.x = reinterpret_cast<unsigned&>(p01);
            u.y = reinterpret_cast<unsigned&>(p23);
            *(uint2*)(g_h1h + (size_t)nn * F1 + tx * 4) = u;
        }
        float ps = f0 * av.x + f1 * av.y + f2 * av.z + f3 * av.w;
        float pd = f0 * dvv.x + f1 * dvv.y + f2 * dvv.z + f3 * dvv.w;
        #pragma unroll
        for (int o = 8; o > 0; o >>= 1) {
            ps += __shfl_xor_sync(0xffffffffu, ps, o);
            pd += __shfl_xor_sync(0xffffffffu, pd, o);
        }
        if ((tx & 15) == 0 && nn < n) {
            g_as1[2 * nn + (tx >> 4)] = ps * LOG2E;
            g_ad1[2 * nn + (tx >> 4)] = pd * LOG2E;
        }
    }
}

// ------- layer-1 gather: 4 nodes/warp, 8 lanes/node, 16 ch/lane ----------------
__global__ void __launch_bounds__(128)
k_gather1(const float* __restrict__ bias1,
          const float* __restrict__ gamma,
          const float* __restrict__ beta, int n) {
    int warp = (blockIdx.x * blockDim.x + threadIdx.x) >> 5;
    int lane = threadIdx.x & 31;
    int quad = lane >> 3;        // 0..3: node within warp
    int sub  = lane & 7;         // 0..7: lane within node-group
    int node = warp * 4 + quad;
    bool valid = node < n;
    if (warp * 4 >= n) return;
    int nd = valid ? node : n;
    int h = sub >> 2;            // subs 0-3: head0 (ch 0..63), 4-7: head1
    float lad = g_ad1[2 * nd + h];
    int c = sub * 16;
    float acc[16] = {}, accB[16] = {};
    float s = 0.f, sB = 0.f;
    // self-loop
    {
        float wv = exp2f(lrelu(g_as1[2 * nd + h] + lad));
        const uint4* hp = (const uint4*)(g_h1h + (size_t)nd * F1 + c);
        uint4 r0 = hp[0], r1 = hp[1];
        float2 f;
        f = h2f2(r0.x); acc[0]  += wv * f.x; acc[1]  += wv * f.y;
        f = h2f2(r0.y); acc[2]  += wv * f.x; acc[3]  += wv * f.y;
        f = h2f2(r0.z); acc[4]  += wv * f.x; acc[5]  += wv * f.y;
        f = h2f2(r0.w); acc[6]  += wv * f.x; acc[7]  += wv * f.y;
        f = h2f2(r1.x); acc[8]  += wv * f.x; acc[9]  += wv * f.y;
        f = h2f2(r1.y); acc[10] += wv * f.x; acc[11] += wv * f.y;
        f = h2f2(r1.z); acc[12] += wv * f.x; acc[13] += wv * f.y;
        f = h2f2(r1.w); acc[14] += wv * f.x; acc[15] += wv * f.y;
        s += wv;
    }
    int e = 0, endp = 0;
    if (valid) { e = g_off[node]; endp = g_off[node + 1]; }
    for (; e < endp; e += 2) {
        int2 q = *(const int2*)&g_csr[e];
        float pA = g_as1[2 * q.x + h];
        float pB = g_as1[2 * q.y + h];
        const uint4* hpA = (const uint4*)(g_h1h + (size_t)q.x * F1 + c);
        const uint4* hpB = (const uint4*)(g_h1h + (size_t)q.y * F1 + c);
        uint4 rA0 = hpA[0], rA1 = hpA[1];
        uint4 rB0 = hpB[0], rB1 = hpB[1];
        float wA = exp2f(lrelu(pA + lad));
        float wB = exp2f(lrelu(pB + lad));
        float2 f;
        f = h2f2(rA0.x); acc[0]  += wA * f.x; acc[1]  += wA * f.y;
        f = h2f2(rA0.y); acc[2]  += wA * f.x; acc[3]  += wA * f.y;
        f = h2f2(rA0.z); acc[4]  += wA * f.x; acc[5]  += wA * f.y;
        f = h2f2(rA0.w); acc[6]  += wA * f.x; acc[7]  += wA * f.y;
        f = h2f2(rA1.x); acc[8]  += wA * f.x; acc[9]  += wA * f.y;
        f = h2f2(rA1.y); acc[10] += wA * f.x; acc[11] += wA * f.y;
        f = h2f2(rA1.z); acc[12] += wA * f.x; acc[13] += wA * f.y;
        f = h2f2(rA1.w); acc[14] += wA * f.x; acc[15] += wA * f.y;
        f = h2f2(rB0.x); accB[0]  += wB * f.x; accB[1]  += wB * f.y;
        f = h2f2(rB0.y); accB[2]  += wB * f.x; accB[3]  += wB * f.y;
        f = h2f2(rB0.z); accB[4]  += wB * f.x; accB[5]  += wB * f.y;
        f = h2f2(rB0.w); accB[6]  += wB * f.x; accB[7]  += wB * f.y;
        f = h2f2(rB1.x); accB[8]  += wB * f.x; accB[9]  += wB * f.y;
        f = h2f2(rB1.y); accB[10] += wB * f.x; accB[11] += wB * f.y;
        f = h2f2(rB1.z); accB[12] += wB * f.x; accB[13] += wB * f.y;
        f = h2f2(rB1.w); accB[14] += wB * f.x; accB[15] += wB * f.y;
        s += wA; sB += wB;
    }
    s += sB;
    float r = 1.f / s;
    float v[16];
    #pragma unroll
    for (int i = 0; i < 16; i += 4) {
        float4 bi = *(const float4*)&bias1[c + i];
        v[i]     = (acc[i]     + accB[i])     * r + bi.x;
        v[i + 1] = (acc[i + 1] + accB[i + 1]) * r + bi.y;
        v[i + 2] = (acc[i + 2] + accB[i + 2]) * r + bi.z;
        v[i + 3] = (acc[i + 3] + accB[i + 3]) * r + bi.w;
    }
    // LayerNorm over 128 channels (8 lanes x 16)
    float tot = 0.f;
    #pragma unroll
    for (int i = 0; i < 16; ++i) tot += v[i];
    #pragma unroll
    for (int o = 4; o > 0; o >>= 1) tot += __shfl_xor_sync(0xffffffffu, tot, o);
    float mu = tot * (1.f / 128.f);
    float sq = 0.f;
    float dv[16];
    #pragma unroll
    for (int i = 0; i < 16; ++i) { dv[i] = v[i] - mu; sq += dv[i] * dv[i]; }
    #pragma unroll
    for (int o = 4; o > 0; o >>= 1) sq += __shfl_xor_sync(0xffffffffu, sq, o);
    float inv = rsqrtf(sq * (1.f / 128.f) + 1e-5f);
    float y[16];
    #pragma unroll
    for (int i = 0; i < 16; i += 4) {
        float4 gm = *(const float4*)&gamma[c + i];
        float4 bt = *(const float4*)&beta[c + i];
        y[i]     = fmaxf(dv[i]     * inv * gm.x + bt.x, 0.f);
        y[i + 1] = fmaxf(dv[i + 1] * inv * gm.y + bt.y, 0.f);
        y[i + 2] = fmaxf(dv[i + 2] * inv * gm.z + bt.z, 0.f);
        y[i + 3] = fmaxf(dv[i + 3] * inv * gm.w + bt.w, 0.f);
    }
    if (valid) {
        uint4 u0, u1;
        __half2 p;
        p = __floats2half2_rn(y[0],  y[1]);  u0.x = reinterpret_cast<unsigned&>(p);
        p = __floats2half2_rn(y[2],  y[3]);  u0.y = reinterpret_cast<unsigned&>(p);
        p = __floats2half2_rn(y[4],  y[5]);  u0.z = reinterpret_cast<unsigned&>(p);
        p = __floats2half2_rn(y[6],  y[7]);  u0.w = reinterpret_cast<unsigned&>(p);
        p = __floats2half2_rn(y[8],  y[9]);  u1.x = reinterpret_cast<unsigned&>(p);
        p = __floats2half2_rn(y[10], y[11]); u1.y = reinterpret_cast<unsigned&>(p);
        p = __floats2half2_rn(y[12], y[13]); u1.z = reinterpret_cast<unsigned&>(p);
        p = __floats2half2_rn(y[14], y[15]); u1.w = reinterpret_cast<unsigned&>(p);
        uint4* op = (uint4*)(g_hlnh + (size_t)node * F1 + c);
        op[0] = u0; op[1] = u1;
    }
    // layer-2 logits
    float sa = 0.f, sd = 0.f;
    #pragma unroll
    for (int i = 0; i < 16; i += 4) {
        float4 ws = *(const float4*)&g_was2[c + i];
        float4 wd = *(const float4*)&g_wad2[c + i];
        sa += y[i] * ws.x + y[i + 1] * ws.y + y[i + 2] * ws.z + y[i + 3] * ws.w;
        sd += y[i] * wd.x + y[i + 1] * wd.y + y[i + 2] * wd.z + y[i + 3] * wd.w;
    }
    #pragma unroll
    for (int o = 4; o > 0; o >>= 1) {
        sa += __shfl_xor_sync(0xffffffffu, sa, o);
        sd += __shfl_xor_sync(0xffffffffu, sd, o);
    }
    if (sub == 0 && valid) { g_as2[node] = sa * LOG2E; g_ad2[node] = sd * LOG2E; }
}

// ---------------- layer-2 projection on TENSOR CORES (HMMA m16n8k16) -----------
__global__ void __launch_bounds__(256)
k4_proj(const float* __restrict__ W2, int n) {
    __shared__ __half W2T[OUTC][136];    // [n][k=0..127 + pad], 17408 B
    int t = threadIdx.x;
    for (int i = t; i < F1 * OUTC; i += 256) {
        int k = i >> 6, c = i & 63;
        W2T[c][k] = __float2half(W2[i]);
    }
    __syncthreads();
    int warp = t >> 5, lane = t & 31;
    int qr = lane >> 2;          // 0..7
    int qc = lane & 3;           // 0..3
    int node0 = blockIdx.x * 128 + warp * 16;
    int rowA = node0 + qr;
    int rowB = node0 + qr + 8;
    const __half* hA = g_hlnh + (size_t)min(rowA, n - 1) * F1;
    const __half* hB = g_hlnh + (size_t)min(rowB, n - 1) * F1;
    float cfr[8][4] = {};
    #pragma unroll
    for (int ks = 0; ks < 8; ++ks) {
        int k0 = ks * 16 + qc * 2;
        unsigned a0 = *(const unsigned*)(hA + k0);
        unsigned a1 = *(const unsigned*)(hB + k0);
        unsigned a2 = *(const unsigned*)(hA + k0 + 8);
        unsigned a3 = *(const unsigned*)(hB + k0 + 8);
        #pragma unroll
        for (int nt = 0; nt < 8; ++nt) {
            int bn = nt * 8 + qr;
            unsigned b0 = *(const unsigned*)&W2T[bn][k0];
            unsigned b1 = *(const unsigned*)&W2T[bn][k0 + 8];
            asm volatile(
                "mma.sync.aligned.m16n8k16.row.col.f32.f16.f16.f32 "
                "{%0,%1,%2,%3}, {%4,%5,%6,%7}, {%8,%9}, {%0,%1,%2,%3};"
                : "+f"(cfr[nt][0]), "+f"(cfr[nt][1]), "+f"(cfr[nt][2]), "+f"(cfr[nt][3])
                : "r"(a0), "r"(a1), "r"(a2), "r"(a3), "r"(b0), "r"(b1));
        }
    }
    bool vA = rowA < n, vB = rowB < n;
    __half* oA = g_h2h + (size_t)rowA * OUTC;
    __half* oB = g_h2h + (size_t)rowB * OUTC;
    #pragma unroll
    for (int nt = 0; nt < 8; ++nt) {
        int col = nt * 8 + qc * 2;
        if (vA) {
            __half2 p = __floats2half2_rn(cfr[nt][0], cfr[nt][1]);
            *(unsigned*)(oA + col) = reinterpret_cast<unsigned&>(p);
        }
        if (vB) {
            __half2 p = __floats2half2_rn(cfr[nt][2], cfr[nt][3]);
            *(unsigned*)(oB + col) = reinterpret_cast<unsigned&>(p);
        }
    }
}

// ------- layer-2 gather: 8 nodes/warp, 4 lanes/node, 16 ch/lane ----------------
// Tail duty: re-zero g_deg for the next kernel_launch call.
__global__ void __launch_bounds__(128)
k_gather2(float* __restrict__ out, const float* __restrict__ bias2, int n) {
    int gtid = blockIdx.x * blockDim.x + threadIdx.x;
    int warp = gtid >> 5;
    int lane = threadIdx.x & 31;
    int oct = lane >> 2;         // 0..7: node within warp
    int sub = lane & 3;          // 0..3
    int node = warp * 8 + oct;
    // zero g_deg for next call (grid threads = 12500 warps * 32 = 400k >= n)
    if (gtid < n) g_deg[gtid] = 0;
    bool valid = node < n;
    if (warp * 8 >= n) return;
    int nd = valid ? node : n;
    float lad = g_ad2[nd];
    int c = sub * 16;
    float acc[16] = {}, accB[16] = {};
    float s = 0.f, sB = 0.f;
    {
        float wv = exp2f(lrelu(g_as2[nd] + lad));
        const uint4* hp = (const uint4*)(g_h2h + (size_t)nd * OUTC + c);
        uint4 r0 = hp[0], r1 = hp[1];
        float2 f;
        f = h2f2(r0.x); acc[0]  += wv * f.x; acc[1]  += wv * f.y;
        f = h2f2(r0.y); acc[2]  += wv * f.x; acc[3]  += wv * f.y;
        f = h2f2(r0.z); acc[4]  += wv * f.x; acc[5]  += wv * f.y;
        f = h2f2(r0.w); acc[6]  += wv * f.x; acc[7]  += wv * f.y;
        f = h2f2(r1.x); acc[8]  += wv * f.x; acc[9]  += wv * f.y;
        f = h2f2(r1.y); acc[10] += wv * f.x; acc[11] += wv * f.y;
        f = h2f2(r1.z); acc[12] += wv * f.x; acc[13] += wv * f.y;
        f = h2f2(r1.w); acc[14] += wv * f.x; acc[15] += wv * f.y;
        s += wv;
    }
    int e = 0, endp = 0;
    if (valid) { e = g_off[node]; endp = g_off[node + 1]; }
    for (; e < endp; e += 2) {
        int2 q = *(const int2*)&g_csr[e];
        float pA = g_as2[q.x];
        float pB = g_as2[q.y];
        const uint4* hpA = (const uint4*)(g_h2h + (size_t)q.x * OUTC + c);
        const uint4* hpB = (const uint4*)(g_h2h + (size_t)q.y * OUTC + c);
        uint4 rA0 = hpA[0], rA1 = hpA[1];
        uint4 rB0 = hpB[0], rB1 = hpB[1];
        float wA = exp2f(lrelu(pA + lad));
        float wB = exp2f(lrelu(pB + lad));
        float2 f;
        f = h2f2(rA0.x); acc[0]  += wA * f.x; acc[1]  += wA * f.y;
        f = h2f2(rA0.y); acc[2]  += wA * f.x; acc[3]  += wA * f.y;
        f = h2f2(rA0.z); acc[4]  += wA * f.x; acc[5]  += wA * f.y;
        f = h2f2(rA0.w); acc[6]  += wA * f.x; acc[7]  += wA * f.y;
        f = h2f2(rA1.x); acc[8]  += wA * f.x; acc[9]  += wA * f.y;
        f = h2f2(rA1.y); acc[10] += wA * f.x; acc[11] += wA * f.y;
        f = h2f2(rA1.z); acc[12] += wA * f.x; acc[13] += wA * f.y;
        f = h2f2(rA1.w); acc[14] += wA * f.x; acc[15] += wA * f.y;
        f = h2f2(rB0.x); accB[0]  += wB * f.x; accB[1]  += wB * f.y;
        f = h2f2(rB0.y); accB[2]  += wB * f.x; accB[3]  += wB * f.y;
        f = h2f2(rB0.z); accB[4]  += wB * f.x; accB[5]  += wB * f.y;
        f = h2f2(rB0.w); accB[6]  += wB * f.x; accB[7]  += wB * f.y;
        f = h2f2(rB1.x); accB[8]  += wB * f.x; accB[9]  += wB * f.y;
        f = h2f2(rB1.y); accB[10] += wB * f.x; accB[11] += wB * f.y;
        f = h2f2(rB1.z); accB[12] += wB * f.x; accB[13] += wB * f.y;
        f = h2f2(rB1.w); accB[14] += wB * f.x; accB[15] += wB * f.y;
        s += wA; sB += wB;
    }
    s += sB;
    if (valid) {
        float r = 1.f / s;
        float* op = out + (size_t)node * OUTC + c;
        #pragma unroll
        for (int i = 0; i < 16; i += 4) {
            float4 bi = *(const float4*)&bias2[c + i];
            float4 o;
            o.x = (acc[i]     + accB[i])     * r + bi.x;
            o.y = (acc[i + 1] + accB[i + 1]) * r + bi.y;
            o.z = (acc[i + 2] + accB[i + 2]) * r + bi.z;
            o.w = (acc[i + 3] + accB[i + 3]) * r + bi.w;
            *(float4*)(op + i) = o;
        }
    }
}

// ---------------- launcher -----------------------------------------------------
extern "C" void kernel_launch(void* const* d_in, const int* in_sizes, int n_in,
                              void* d_out, int out_size) {
    const float* x     = (const float*)d_in[0];
    const int*   ei    = (const int*)  d_in[1];
    const float* W1    = (const float*)d_in[2];
    const float* as1   = (const float*)d_in[3];
    const float* ad1   = (const float*)d_in[4];
    const float* b1    = (const float*)d_in[5];
    const float* gamma = (const float*)d_in[6];
    const float* beta  = (const float*)d_in[7];
    const float* W2    = (const float*)d_in[8];
    const float* as2   = (const float*)d_in[9];
    const float* ad2   = (const float*)d_in[10];
    const float* b2    = (const float*)d_in[11];
    float* out = (float*)d_out;

    int n = in_sizes[0] / IN_DIM;
    int E = in_sizes[1] / 2;
    const int* srcp = ei;
    const int* dstp = ei + E;

    int proj_blocks = (n + 31) / 32;
    int g1_blocks = (((n + 3) / 4) + 3) / 4;     // 4 nodes/warp, 4 warps/block
    int g2_blocks = (((n + 7) / 8) + 3) / 4;     // 8 nodes/warp, 4 warps/block

    k_mega<<<CSR_BLOCKS + proj_blocks, 256>>>(srcp, dstp, E, n,
                                              x, W1, as1, ad1, W2, as2, ad2);  // 1
    k_gather1<<<g1_blocks, 128>>>(b1, gamma, beta, n);                         // 2
    k4_proj<<<(n + 127) / 128, 256>>>(W2, n);                                  // 3
    k_gather2<<<g2_blocks, 128>>>(out, b2, n);                                 // 4
}

// round 15
// speedup vs baseline: 1.0384x; 1.0384x over previous
#include <cuda_runtime.h>
#include <cuda_fp16.h>

#define N_NODES 100000
#define E_EDGES 1600000
#define IN_DIM 32
#define HID 64
#define NHEADS 2
#define F1 128   // NHEADS*HID
#define OUTC 64
#define LOG2E 1.4426950408889634f

#define CSR_BLOCKS 512
#define CSR_THREADS 256

// ---------------- scratch (device globals; no allocation allowed) ------------
__device__ __align__(16) __half g_h1h [(size_t)(N_NODES + 1) * F1];
__device__ __align__(16) __half g_hlnh[(size_t)N_NODES * F1];
__device__ __align__(16) __half g_h2h [(size_t)(N_NODES + 1) * OUTC];
__device__ __align__(16) float g_as1[(N_NODES + 1) * NHEADS];
__device__ __align__(16) float g_ad1[(N_NODES + 1) * NHEADS];
__device__ float g_as2[N_NODES + 1];
__device__ float g_ad2[N_NODES + 1];
__device__ int   g_deg[N_NODES];          // ZERO at kernel_launch entry (BSS init + tail-zeroed by k_gather2)
__device__ int   g_off[N_NODES + 1];
__device__ int   g_cur[N_NODES];
__device__ __align__(16) int g_csr[E_EDGES + 3 * N_NODES + 8];
__device__ int   g_bsum[CSR_BLOCKS];
__device__ int   g_bscan[CSR_BLOCKS];
__device__ __align__(16) float g_was2[F1];
__device__ __align__(16) float g_wad2[F1];
__device__ int   g_bar_count;
__device__ int   g_bar_gen;

__device__ __forceinline__ float lrelu(float v) { return v > 0.f ? v : 0.2f * v; }

// ---- packed fp32x2 helpers ----------------------------------------------------
__device__ __forceinline__ unsigned long long packdup(float a) {
    unsigned long long r;
    asm("mov.b64 %0, {%1, %1};" : "=l"(r) : "f"(a));
    return r;
}
__device__ __forceinline__ void ffma2(unsigned long long& acc,
                                      unsigned long long a, unsigned long long b) {
    asm("fma.rn.f32x2 %0, %1, %2, %0;" : "+l"(acc) : "l"(a), "l"(b));
}
__device__ __forceinline__ float lo32(unsigned long long v) {
    return __uint_as_float((unsigned)(v & 0xffffffffull));
}
__device__ __forceinline__ float hi32(unsigned long long v) {
    return __uint_as_float((unsigned)(v >> 32));
}
__device__ __forceinline__ float2 h2f2(unsigned h) {
    return __half22float2(reinterpret_cast<__half2&>(h));
}

// ---- software grid barrier (csr blocks only) -----------------------------------
__device__ __forceinline__ void gsync() {
    __syncthreads();
    __threadfence();
    if (threadIdx.x == 0) {
        int gen = *(volatile int*)&g_bar_gen;
        if (atomicAdd(&g_bar_count, 1) == CSR_BLOCKS - 1) {
            g_bar_count = 0;
            __threadfence();
            *(volatile int*)&g_bar_gen = gen + 1;
        } else {
            while (*(volatile int*)&g_bar_gen == gen) { }
        }
        __threadfence();
    }
    __syncthreads();
}

// ===== mega kernel: blocks [0,512) build CSR; blocks [512,...) do fold2+proj1 ===
// PRECONDITION: g_deg == 0 (BSS at load; re-zeroed by k_gather2 tail each call)
__global__ void __launch_bounds__(256, 4)
k_mega(const int* __restrict__ src, const int* __restrict__ dst, int E, int n,
       const float* __restrict__ x, const float* __restrict__ W1,
       const float* __restrict__ attS, const float* __restrict__ attD,
       const float* __restrict__ W2,
       const float* __restrict__ as2v, const float* __restrict__ ad2v) {
    __shared__ __align__(16) float Ws[IN_DIM * F1];      // proj: weights | csr: wsum alias
    __shared__ __align__(16) float xsT[IN_DIM][36];
    int t = threadIdx.x;

    if (blockIdx.x < CSR_BLOCKS) {
        // -------------------- CSR path --------------------
        int* wsum = (int*)xsT;
        const int T = CSR_BLOCKS * CSR_THREADS;
        int gt = blockIdx.x * CSR_THREADS + t;
        int lane = t & 31, w = t >> 5;

        // P1: count degrees (2 int4 chunks in flight)
        int E4 = E >> 2;
        int i = gt;
        for (; i + T < E4; i += 2 * T) {
            int4 a = ((const int4*)dst)[i];
            int4 b = ((const int4*)dst)[i + T];
            atomicAdd(&g_deg[a.x], 1); atomicAdd(&g_deg[a.y], 1);
            atomicAdd(&g_deg[a.z], 1); atomicAdd(&g_deg[a.w], 1);
            atomicAdd(&g_deg[b.x], 1); atomicAdd(&g_deg[b.y], 1);
            atomicAdd(&g_deg[b.z], 1); atomicAdd(&g_deg[b.w], 1);
        }
        if (i < E4) {
            int4 a = ((const int4*)dst)[i];
            atomicAdd(&g_deg[a.x], 1); atomicAdd(&g_deg[a.y], 1);
            atomicAdd(&g_deg[a.z], 1); atomicAdd(&g_deg[a.w], 1);
        }
        for (int e = E4 * 4 + gt; e < E; e += T) atomicAdd(&g_deg[dst[e]], 1);
        gsync();
        // P2: per-thread chunk sum (padded to 4) + block scan
        int C = (n + T - 1) / T;
        int b0 = gt * C;
        int s = 0;
        for (int j = 0; j < C; ++j) {
            int idx = b0 + j;
            if (idx < n) s += (g_deg[idx] + 3) & ~3;
        }
        int incl = s;
        #pragma unroll
        for (int o = 1; o < 32; o <<= 1) {
            int xv = __shfl_up_sync(0xffffffffu, incl, o);
            if (lane >= o) incl += xv;
        }
        if (lane == 31) wsum[w] = incl;
        __syncthreads();
        if (t < 8) {
            int xv = wsum[t];
            #pragma unroll
            for (int o = 1; o < 8; o <<= 1) {
                int y = __shfl_up_sync(0xffu, xv, o);
                if (t >= o) xv += y;
            }
            wsum[t] = xv;
        }
        __syncthreads();
        int excl = incl - s + (w > 0 ? wsum[w - 1] : 0);
        if (t == CSR_THREADS - 1) g_bsum[blockIdx.x] = excl + s;
        gsync();
        // P3: block 0 scans block totals
        if (blockIdx.x == 0) {
            int a0 = g_bsum[2 * t], a1 = g_bsum[2 * t + 1];
            int ss = a0 + a1;
            int in2 = ss;
            #pragma unroll
            for (int o = 1; o < 32; o <<= 1) {
                int xv = __shfl_up_sync(0xffffffffu, in2, o);
                if (lane >= o) in2 += xv;
            }
            if (lane == 31) wsum[w] = in2;
            __syncthreads();
            if (t < 8) {
                int xv = wsum[t];
                #pragma unroll
                for (int o = 1; o < 8; o <<= 1) {
                    int y = __shfl_up_sync(0xffu, xv, o);
                    if (t >= o) xv += y;
                }
                wsum[t] = xv;
            }
            __syncthreads();
            int ex2 = in2 - ss + (w > 0 ? wsum[w - 1] : 0);
            g_bscan[2 * t]     = ex2;
            g_bscan[2 * t + 1] = ex2 + a0;
        }
        gsync();
        // P4: write offsets (padded), fill pad slots with dummy node n
        int off = excl + g_bscan[blockIdx.x];
        for (int j = 0; j < C; ++j) {
            int idx = b0 + j;
            if (idx < n) {
                int d = g_deg[idx];
                int p = (d + 3) & ~3;
                g_off[idx] = off;
                g_cur[idx] = off;
                for (int k = d; k < p; ++k) g_csr[off + k] = n;  // dummy
                if (idx == n - 1) g_off[n] = off + p;
                off += p;
            }
        }
        gsync();
        // P5: scatter (2 chunks in flight)
        i = gt;
        for (; i + T < E4; i += 2 * T) {
            int4 sa = ((const int4*)src)[i];
            int4 da = ((const int4*)dst)[i];
            int4 sb = ((const int4*)src)[i + T];
            int4 db = ((const int4*)dst)[i + T];
            g_csr[atomicAdd(&g_cur[da.x], 1)] = sa.x;
            g_csr[atomicAdd(&g_cur[da.y], 1)] = sa.y;
            g_csr[atomicAdd(&g_cur[da.z], 1)] = sa.z;
            g_csr[atomicAdd(&g_cur[da.w], 1)] = sa.w;
            g_csr[atomicAdd(&g_cur[db.x], 1)] = sb.x;
            g_csr[atomicAdd(&g_cur[db.y], 1)] = sb.y;
            g_csr[atomicAdd(&g_cur[db.z], 1)] = sb.z;
            g_csr[atomicAdd(&g_cur[db.w], 1)] = sb.w;
        }
        if (i < E4) {
            int4 sa = ((const int4*)src)[i];
            int4 da = ((const int4*)dst)[i];
            g_csr[atomicAdd(&g_cur[da.x], 1)] = sa.x;
            g_csr[atomicAdd(&g_cur[da.y], 1)] = sa.y;
            g_csr[atomicAdd(&g_cur[da.z], 1)] = sa.z;
            g_csr[atomicAdd(&g_cur[da.w], 1)] = sa.w;
        }
        for (int e = E4 * 4 + gt; e < E; e += T) {
            g_csr[atomicAdd(&g_cur[dst[e]], 1)] = src[e];
        }
        return;
    }

    // -------------------- fold2 + proj1 path --------------------
    int pb = blockIdx.x - CSR_BLOCKS;
    if (pb == 0) {
        if (t < F1) {
            float s = 0.f, d = 0.f;
            for (int c = 0; c < OUTC; ++c) {
                float wv = W2[t * OUTC + c];
                s += wv * as2v[c];
                d += wv * ad2v[c];
            }
            g_was2[t] = s;
            g_wad2[t] = d;
            g_h1h[(size_t)n * F1 + t] = __float2half(0.f);
        }
        if (t < 2) { g_as1[2 * n + t] = -1e30f; g_ad1[2 * n + t] = 0.f; }
        if (t == 0) { g_as2[n] = -1e30f; g_ad2[n] = 0.f; }
        if (t < OUTC) g_h2h[(size_t)n * OUTC + t] = __float2half(0.f);
    }
    for (int i = t; i < IN_DIM * F1; i += 256) Ws[i] = W1[i];
    int base = pb * 32;
    #pragma unroll
    for (int i = 0; i < 4; ++i) {
        int idx = t + i * 256;
        int node = idx >> 5, k = idx & 31;
        int nn = base + node;
        xsT[k][node] = (nn < n) ? x[(size_t)nn * IN_DIM + k] : 0.f;
    }
    __syncthreads();
    int tx = t & 31;
    int ty = t >> 5;
    unsigned long long acc[4][2] = {};
    #pragma unroll
    for (int k = 0; k < IN_DIM; ++k) {
        ulonglong2 w = *(const ulonglong2*)&Ws[k * F1 + tx * 4];
        float4 xv = *(const float4*)&xsT[k][ty * 4];
        unsigned long long xp0 = packdup(xv.x), xp1 = packdup(xv.y);
        unsigned long long xp2 = packdup(xv.z), xp3 = packdup(xv.w);
        ffma2(acc[0][0], w.x, xp0); ffma2(acc[0][1], w.y, xp0);
        ffma2(acc[1][0], w.x, xp1); ffma2(acc[1][1], w.y, xp1);
        ffma2(acc[2][0], w.x, xp2); ffma2(acc[2][1], w.y, xp2);
        ffma2(acc[3][0], w.x, xp3); ffma2(acc[3][1], w.y, xp3);
    }
    float4 av = __ldg((const float4*)&attS[tx * 4]);
    float4 dvv = __ldg((const float4*)&attD[tx * 4]);
    #pragma unroll
    for (int i = 0; i < 4; ++i) {
        int nn = base + ty * 4 + i;
        float f0 = lo32(acc[i][0]), f1 = hi32(acc[i][0]);
        float f2 = lo32(acc[i][1]), f3 = hi32(acc[i][1]);
        if (nn < n) {
            __half2 p01 = __floats2half2_rn(f0, f1);
            __half2 p23 = __floats2half2_rn(f2, f3);
            uint2 u;
            u.x = reinterpret_cast<unsigned&>(p01);
            u.y = reinterpret_cast<unsigned&>(p23);
            *(uint2*)(g_h1h + (size_t)nn * F1 + tx * 4) = u;
        }
        float ps = f0 * av.x + f1 * av.y + f2 * av.z + f3 * av.w;
        float pd = f0 * dvv.x + f1 * dvv.y + f2 * dvv.z + f3 * dvv.w;
        #pragma unroll
        for (int o = 8; o > 0; o >>= 1) {
            ps += __shfl_xor_sync(0xffffffffu, ps, o);
            pd += __shfl_xor_sync(0xffffffffu, pd, o);
        }
        if ((tx & 15) == 0 && nn < n) {
            g_as1[2 * nn + (tx >> 4)] = ps * LOG2E;
            g_ad1[2 * nn + (tx >> 4)] = pd * LOG2E;
        }
    }
}

// ------- layer-1 gather: 2 nodes/warp, 16 lanes/node, 8 ch/lane ----------------
__global__ void __launch_bounds__(256)
k_gather1(const float* __restrict__ bias1,
          const float* __restrict__ gamma,
          const float* __restrict__ beta, int n) {
    int warp = (blockIdx.x * blockDim.x + threadIdx.x) >> 5;
    int lane = threadIdx.x & 31;
    int half = lane >> 4;
    int sub  = lane & 15;
    int node = warp * 2 + half;
    bool valid = node < n;
    if (warp * 2 >= n) return;
    int nd = valid ? node : n;
    int h = sub >> 3;
    float lad = g_ad1[2 * nd + h];
    float acc[8] = {}, accB[8] = {};
    float s = 0.f, sB = 0.f;
    // self-loop
    {
        float wv = exp2f(lrelu(g_as1[2 * nd + h] + lad));
        uint4 r = *(const uint4*)(g_h1h + (size_t)nd * F1 + sub * 8);
        float2 f;
        f = h2f2(r.x); acc[0] += wv * f.x; acc[1] += wv * f.y;
        f = h2f2(r.y); acc[2] += wv * f.x; acc[3] += wv * f.y;
        f = h2f2(r.z); acc[4] += wv * f.x; acc[5] += wv * f.y;
        f = h2f2(r.w); acc[6] += wv * f.x; acc[7] += wv * f.y;
        s += wv;
    }
    int e = 0, endp = 0;
    if (valid) { e = g_off[node]; endp = g_off[node + 1]; }
    for (; e < endp; e += 2) {
        int2 q = *(const int2*)&g_csr[e];
        float pA = g_as1[2 * q.x + h];
        float pB = g_as1[2 * q.y + h];
        uint4 rA = *(const uint4*)(g_h1h + (size_t)q.x * F1 + sub * 8);
        uint4 rB = *(const uint4*)(g_h1h + (size_t)q.y * F1 + sub * 8);
        float wA = exp2f(lrelu(pA + lad));
        float wB = exp2f(lrelu(pB + lad));
        float2 f;
        f = h2f2(rA.x); acc[0]  += wA * f.x; acc[1]  += wA * f.y;
        f = h2f2(rA.y); acc[2]  += wA * f.x; acc[3]  += wA * f.y;
        f = h2f2(rA.z); acc[4]  += wA * f.x; acc[5]  += wA * f.y;
        f = h2f2(rA.w); acc[6]  += wA * f.x; acc[7]  += wA * f.y;
        f = h2f2(rB.x); accB[0] += wB * f.x; accB[1] += wB * f.y;
        f = h2f2(rB.y); accB[2] += wB * f.x; accB[3] += wB * f.y;
        f = h2f2(rB.z); accB[4] += wB * f.x; accB[5] += wB * f.y;
        f = h2f2(rB.w); accB[6] += wB * f.x; accB[7] += wB * f.y;
        s += wA; sB += wB;
    }
    s += sB;
    float r = 1.f / s;
    int c = sub * 8;
    float4 bi0 = *(const float4*)&bias1[c];
    float4 bi1 = *(const float4*)&bias1[c + 4];
    float v[8];
    v[0] = (acc[0] + accB[0]) * r + bi0.x;
    v[1] = (acc[1] + accB[1]) * r + bi0.y;
    v[2] = (acc[2] + accB[2]) * r + bi0.z;
    v[3] = (acc[3] + accB[3]) * r + bi0.w;
    v[4] = (acc[4] + accB[4]) * r + bi1.x;
    v[5] = (acc[5] + accB[5]) * r + bi1.y;
    v[6] = (acc[6] + accB[6]) * r + bi1.z;
    v[7] = (acc[7] + accB[7]) * r + bi1.w;
    float tot = 0.f;
    #pragma unroll
    for (int i = 0; i < 8; ++i) tot += v[i];
    #pragma unroll
    for (int o = 8; o > 0; o >>= 1) tot += __shfl_xor_sync(0xffffffffu, tot, o);
    float mu = tot * (1.f / 128.f);
    float sq = 0.f;
    float dv[8];
    #pragma unroll
    for (int i = 0; i < 8; ++i) { dv[i] = v[i] - mu; sq += dv[i] * dv[i]; }
    #pragma unroll
    for (int o = 8; o > 0; o >>= 1) sq += __shfl_xor_sync(0xffffffffu, sq, o);
    float inv = rsqrtf(sq * (1.f / 128.f) + 1e-5f);
    float4 gm0 = *(const float4*)&gamma[c];
    float4 gm1 = *(const float4*)&gamma[c + 4];
    float4 bt0 = *(const float4*)&beta[c];
    float4 bt1 = *(const float4*)&beta[c + 4];
    float y[8];
    y[0] = fmaxf(dv[0] * inv * gm0.x + bt0.x, 0.f);
    y[1] = fmaxf(dv[1] * inv * gm0.y + bt0.y, 0.f);
    y[2] = fmaxf(dv[2] * inv * gm0.z + bt0.z, 0.f);
    y[3] = fmaxf(dv[3] * inv * gm0.w + bt0.w, 0.f);
    y[4] = fmaxf(dv[4] * inv * gm1.x + bt1.x, 0.f);
    y[5] = fmaxf(dv[5] * inv * gm1.y + bt1.y, 0.f);
    y[6] = fmaxf(dv[6] * inv * gm1.z + bt1.z, 0.f);
    y[7] = fmaxf(dv[7] * inv * gm1.w + bt1.w, 0.f);
    if (valid) {
        __half2 p0 = __floats2half2_rn(y[0], y[1]);
        __half2 p1 = __floats2half2_rn(y[2], y[3]);
        __half2 p2 = __floats2half2_rn(y[4], y[5]);
        __half2 p3 = __floats2half2_rn(y[6], y[7]);
        uint4 u;
        u.x = reinterpret_cast<unsigned&>(p0);
        u.y = reinterpret_cast<unsigned&>(p1);
        u.z = reinterpret_cast<unsigned&>(p2);
        u.w = reinterpret_cast<unsigned&>(p3);
        *(uint4*)(g_hlnh + (size_t)node * F1 + c) = u;
    }
    float4 ws0 = *(const float4*)&g_was2[c];
    float4 ws1 = *(const float4*)&g_was2[c + 4];
    float4 wd0 = *(const float4*)&g_wad2[c];
    float4 wd1 = *(const float4*)&g_wad2[c + 4];
    float sa = y[0] * ws0.x + y[1] * ws0.y + y[2] * ws0.z + y[3] * ws0.w
             + y[4] * ws1.x + y[5] * ws1.y + y[6] * ws1.z + y[7] * ws1.w;
    float sd = y[0] * wd0.x + y[1] * wd0.y + y[2] * wd0.z + y[3] * wd0.w
             + y[4] * wd1.x + y[5] * wd1.y + y[6] * wd1.z + y[7] * wd1.w;
    #pragma unroll
    for (int o = 8; o > 0; o >>= 1) {
        sa += __shfl_xor_sync(0xffffffffu, sa, o);
        sd += __shfl_xor_sync(0xffffffffu, sd, o);
    }
    if (sub == 0 && valid) { g_as2[node] = sa * LOG2E; g_ad2[node] = sd * LOG2E; }
}

// ---------------- layer-2 projection on TENSOR CORES (HMMA m16n8k16) -----------
__global__ void __launch_bounds__(256)
k4_proj(const float* __restrict__ W2, int n) {
    __shared__ __half W2T[OUTC][136];    // [n][k=0..127 + pad], 17408 B
    int t = threadIdx.x;
    for (int i = t; i < F1 * OUTC; i += 256) {
        int k = i >> 6, c = i & 63;
        W2T[c][k] = __float2half(W2[i]);
    }
    __syncthreads();
    int warp = t >> 5, lane = t & 31;
    int qr = lane >> 2;          // 0..7
    int qc = lane & 3;           // 0..3
    int node0 = blockIdx.x * 128 + warp * 16;
    int rowA = node0 + qr;
    int rowB = node0 + qr + 8;
    const __half* hA = g_hlnh + (size_t)min(rowA, n - 1) * F1;
    const __half* hB = g_hlnh + (size_t)min(rowB, n - 1) * F1;
    float cfr[8][4] = {};
    #pragma unroll
    for (int ks = 0; ks < 8; ++ks) {
        int k0 = ks * 16 + qc * 2;
        unsigned a0 = *(const unsigned*)(hA + k0);
        unsigned a1 = *(const unsigned*)(hB + k0);
        unsigned a2 = *(const unsigned*)(hA + k0 + 8);
        unsigned a3 = *(const unsigned*)(hB + k0 + 8);
        #pragma unroll
        for (int nt = 0; nt < 8; ++nt) {
            int bn = nt * 8 + qr;
            unsigned b0 = *(const unsigned*)&W2T[bn][k0];
            unsigned b1 = *(const unsigned*)&W2T[bn][k0 + 8];
            asm volatile(
                "mma.sync.aligned.m16n8k16.row.col.f32.f16.f16.f32 "
                "{%0,%1,%2,%3}, {%4,%5,%6,%7}, {%8,%9}, {%0,%1,%2,%3};"
                : "+f"(cfr[nt][0]), "+f"(cfr[nt][1]), "+f"(cfr[nt][2]), "+f"(cfr[nt][3])
                : "r"(a0), "r"(a1), "r"(a2), "r"(a3), "r"(b0), "r"(b1));
        }
    }
    bool vA = rowA < n, vB = rowB < n;
    __half* oA = g_h2h + (size_t)rowA * OUTC;
    __half* oB = g_h2h + (size_t)rowB * OUTC;
    #pragma unroll
    for (int nt = 0; nt < 8; ++nt) {
        int col = nt * 8 + qc * 2;
        if (vA) {
            __half2 p = __floats2half2_rn(cfr[nt][0], cfr[nt][1]);
            *(unsigned*)(oA + col) = reinterpret_cast<unsigned&>(p);
        }
        if (vB) {
            __half2 p = __floats2half2_rn(cfr[nt][2], cfr[nt][3]);
            *(unsigned*)(oB + col) = reinterpret_cast<unsigned&>(p);
        }
    }
}

// ------- layer-2 gather: 4 nodes/warp, 8 lanes/node, 8 ch/lane -----------------
// Tail duty: re-zero g_deg for the next kernel_launch call.
__global__ void __launch_bounds__(256)
k_gather2(float* __restrict__ out, const float* __restrict__ bias2, int n) {
    int gtid = blockIdx.x * blockDim.x + threadIdx.x;
    int warp = gtid >> 5;
    int lane = threadIdx.x & 31;
    int quad = lane >> 3;
    int sub  = lane & 7;
    int node = warp * 4 + quad;
    if (gtid < n) g_deg[gtid] = 0;
    bool valid = node < n;
    if (warp * 4 >= n) return;
    int nd = valid ? node : n;
    float lad = g_ad2[nd];
    float acc[8] = {}, accB[8] = {};
    float s = 0.f, sB = 0.f;
    {
        float wv = exp2f(lrelu(g_as2[nd] + lad));
        uint4 r = *(const uint4*)(g_h2h + (size_t)nd * OUTC + sub * 8);
        float2 f;
        f = h2f2(r.x); acc[0] += wv * f.x; acc[1] += wv * f.y;
        f = h2f2(r.y); acc[2] += wv * f.x; acc[3] += wv * f.y;
        f = h2f2(r.z); acc[4] += wv * f.x; acc[5] += wv * f.y;
        f = h2f2(r.w); acc[6] += wv * f.x; acc[7] += wv * f.y;
        s += wv;
    }
    int e = 0, endp = 0;
    if (valid) { e = g_off[node]; endp = g_off[node + 1]; }
    for (; e < endp; e += 2) {
        int2 q = *(const int2*)&g_csr[e];
        float pA = g_as2[q.x];
        float pB = g_as2[q.y];
        uint4 rA = *(const uint4*)(g_h2h + (size_t)q.x * OUTC + sub * 8);
        uint4 rB = *(const uint4*)(g_h2h + (size_t)q.y * OUTC + sub * 8);
        float wA = exp2f(lrelu(pA + lad));
        float wB = exp2f(lrelu(pB + lad));
        float2 f;
        f = h2f2(rA.x); acc[0]  += wA * f.x; acc[1]  += wA * f.y;
        f = h2f2(rA.y); acc[2]  += wA * f.x; acc[3]  += wA * f.y;
        f = h2f2(rA.z); acc[4]  += wA * f.x; acc[5]  += wA * f.y;
        f = h2f2(rA.w); acc[6]  += wA * f.x; acc[7]  += wA * f.y;
        f = h2f2(rB.x); accB[0] += wB * f.x; accB[1] += wB * f.y;
        f = h2f2(rB.y); accB[2] += wB * f.x; accB[3] += wB * f.y;
        f = h2f2(rB.z); accB[4] += wB * f.x; accB[5] += wB * f.y;
        f = h2f2(rB.w); accB[6] += wB * f.x; accB[7] += wB * f.y;
        s += wA; sB += wB;
    }
    s += sB;
    if (valid) {
        float r = 1.f / s;
        int c = sub * 8;
        float4 bi0 = *(const float4*)&bias2[c];
        float4 bi1 = *(const float4*)&bias2[c + 4];
        float4 o0, o1;
        o0.x = (acc[0] + accB[0]) * r + bi0.x;
        o0.y = (acc[1] + accB[1]) * r + bi0.y;
        o0.z = (acc[2] + accB[2]) * r + bi0.z;
        o0.w = (acc[3] + accB[3]) * r + bi0.w;
        o1.x = (acc[4] + accB[4]) * r + bi1.x;
        o1.y = (acc[5] + accB[5]) * r + bi1.y;
        o1.z = (acc[6] + accB[6]) * r + bi1.z;
        o1.w = (acc[7] + accB[7]) * r + bi1.w;
        *(float4*)(out + (size_t)node * OUTC + c)     = o0;
        *(float4*)(out + (size_t)node * OUTC + c + 4) = o1;
    }
}

// ---------------- launcher -----------------------------------------------------
extern "C" void kernel_launch(void* const* d_in, const int* in_sizes, int n_in,
                              void* d_out, int out_size) {
    const float* x     = (const float*)d_in[0];
    const int*   ei    = (const int*)  d_in[1];
    const float* W1    = (const float*)d_in[2];
    const float* as1   = (const float*)d_in[3];
    const float* ad1   = (const float*)d_in[4];
    const float* b1    = (const float*)d_in[5];
    const float* gamma = (const float*)d_in[6];
    const float* beta  = (const float*)d_in[7];
    const float* W2    = (const float*)d_in[8];
    const float* as2   = (const float*)d_in[9];
    const float* ad2   = (const float*)d_in[10];
    const float* b2    = (const float*)d_in[11];
    float* out = (float*)d_out;

    int n = in_sizes[0] / IN_DIM;
    int E = in_sizes[1] / 2;
    const int* srcp = ei;
    const int* dstp = ei + E;

    int proj_blocks = (n + 31) / 32;
    int g1_blocks = (((n + 1) / 2) + 7) / 8;     // 2 nodes/warp, 8 warps/block
    int g2_blocks = (((n + 3) / 4) + 7) / 8;     // 4 nodes/warp, 8 warps/block

    k_mega<<<CSR_BLOCKS + proj_blocks, 256>>>(srcp, dstp, E, n,
                                              x, W1, as1, ad1, W2, as2, ad2);  // 1
    k_gather1<<<g1_blocks, 256>>>(b1, gamma, beta, n);                         // 2
    k4_proj<<<(n + 127) / 128, 256>>>(W2, n);                                  // 3
    k_gather2<<<g2_blocks, 256>>>(out, b2, n);                                 // 4
}

// round 16
// speedup vs baseline: 1.0658x; 1.0264x over previous
#include <cuda_runtime.h>
#include <cuda_fp16.h>

#define N_NODES 100000
#define E_EDGES 1600000
#define IN_DIM 32
#define HID 64
#define NHEADS 2
#define F1 128   // NHEADS*HID
#define OUTC 64
#define LOG2E 1.4426950408889634f

#define CSR_BLOCKS 512
#define CSR_THREADS 256

// ---------------- scratch (device globals; no allocation allowed) ------------
__device__ __align__(16) __half g_h1h [(size_t)(N_NODES + 1) * F1];
__device__ __align__(16) __half g_hlnh[(size_t)N_NODES * F1];
__device__ __align__(16) __half g_h2h [(size_t)(N_NODES + 1) * OUTC];
__device__ __align__(16) float g_as1[(N_NODES + 1) * NHEADS];
__device__ __align__(16) float g_ad1[(N_NODES + 1) * NHEADS];
__device__ float g_as2[N_NODES + 1];
__device__ float g_ad2[N_NODES + 1];
__device__ int   g_deg[N_NODES];          // ZERO at kernel_launch entry (BSS init + tail-zeroed by k_gather2)
__device__ int   g_off[N_NODES + 1];
__device__ int   g_cur[N_NODES];
__device__ __align__(16) int g_csr[E_EDGES + 3 * N_NODES + 8];
__device__ int   g_bsum[CSR_BLOCKS];
__device__ int   g_bar_count;
__device__ int   g_bar_gen;
__device__ __align__(16) float g_was2[F1];
__device__ __align__(16) float g_wad2[F1];

__device__ __forceinline__ float lrelu(float v) { return v > 0.f ? v : 0.2f * v; }

// ---- packed fp32x2 helpers ----------------------------------------------------
__device__ __forceinline__ unsigned long long packdup(float a) {
    unsigned long long r;
    asm("mov.b64 %0, {%1, %1};" : "=l"(r) : "f"(a));
    return r;
}
__device__ __forceinline__ void ffma2(unsigned long long& acc,
                                      unsigned long long a, unsigned long long b) {
    asm("fma.rn.f32x2 %0, %1, %2, %0;" : "+l"(acc) : "l"(a), "l"(b));
}
__device__ __forceinline__ float lo32(unsigned long long v) {
    return __uint_as_float((unsigned)(v & 0xffffffffull));
}
__device__ __forceinline__ float hi32(unsigned long long v) {
    return __uint_as_float((unsigned)(v >> 32));
}
__device__ __forceinline__ float2 h2f2(unsigned h) {
    return __half22float2(reinterpret_cast<__half2&>(h));
}

// ---- software grid barrier (csr blocks only) -----------------------------------
__device__ __forceinline__ void gsync() {
    __syncthreads();
    __threadfence();
    if (threadIdx.x == 0) {
        int gen = *(volatile int*)&g_bar_gen;
        if (atomicAdd(&g_bar_count, 1) == CSR_BLOCKS - 1) {
            g_bar_count = 0;
            __threadfence();
            *(volatile int*)&g_bar_gen = gen + 1;
        } else {
            while (*(volatile int*)&g_bar_gen == gen) { }
        }
        __threadfence();
    }
    __syncthreads();
}

// ===== mega kernel: blocks [0,512) build CSR; blocks [512,...) do fold2+proj1 ===
// PRECONDITION: g_deg == 0 (BSS at load; re-zeroed by k_gather2 tail each call)
__global__ void __launch_bounds__(256, 4)
k_mega(const int* __restrict__ src, const int* __restrict__ dst, int E, int n,
       const float* __restrict__ x, const float* __restrict__ W1,
       const float* __restrict__ attS, const float* __restrict__ attD,
       const float* __restrict__ W2,
       const float* __restrict__ as2v, const float* __restrict__ ad2v) {
    __shared__ __align__(16) float Ws[IN_DIM * F1];      // proj: weights | csr: wsum alias
    __shared__ __align__(16) float xsT[IN_DIM][36];
    int t = threadIdx.x;

    if (blockIdx.x < CSR_BLOCKS) {
        // -------------------- CSR path --------------------
        int* wsum = (int*)xsT;
        const int T = CSR_BLOCKS * CSR_THREADS;
        int gt = blockIdx.x * CSR_THREADS + t;
        int lane = t & 31, w = t >> 5;

        // P1: count degrees (2 int4 chunks in flight)
        int E4 = E >> 2;
        int i = gt;
        for (; i + T < E4; i += 2 * T) {
            int4 a = ((const int4*)dst)[i];
            int4 b = ((const int4*)dst)[i + T];
            atomicAdd(&g_deg[a.x], 1); atomicAdd(&g_deg[a.y], 1);
            atomicAdd(&g_deg[a.z], 1); atomicAdd(&g_deg[a.w], 1);
            atomicAdd(&g_deg[b.x], 1); atomicAdd(&g_deg[b.y], 1);
            atomicAdd(&g_deg[b.z], 1); atomicAdd(&g_deg[b.w], 1);
        }
        if (i < E4) {
            int4 a = ((const int4*)dst)[i];
            atomicAdd(&g_deg[a.x], 1); atomicAdd(&g_deg[a.y], 1);
            atomicAdd(&g_deg[a.z], 1); atomicAdd(&g_deg[a.w], 1);
        }
        for (int e = E4 * 4 + gt; e < E; e += T) atomicAdd(&g_deg[dst[e]], 1);
        gsync();
        // P2: per-thread chunk sum (padded to 4) + block scan -> g_bsum
        int C = (n + T - 1) / T;
        int b0 = gt * C;
        int s = 0;
        for (int j = 0; j < C; ++j) {
            int idx = b0 + j;
            if (idx < n) s += (g_deg[idx] + 3) & ~3;
        }
        int incl = s;
        #pragma unroll
        for (int o = 1; o < 32; o <<= 1) {
            int xv = __shfl_up_sync(0xffffffffu, incl, o);
            if (lane >= o) incl += xv;
        }
        if (lane == 31) wsum[w] = incl;
        __syncthreads();
        if (t < 8) {
            int xv = wsum[t];
            #pragma unroll
            for (int o = 1; o < 8; o <<= 1) {
                int y = __shfl_up_sync(0xffu, xv, o);
                if (t >= o) xv += y;
            }
            wsum[t] = xv;
        }
        __syncthreads();
        int excl = incl - s + (w > 0 ? wsum[w - 1] : 0);
        if (t == CSR_THREADS - 1) g_bsum[blockIdx.x] = excl + s;
        gsync();
        // P3 (barrier-free): every block reduces its own prefix of g_bsum
        {
            int part = 0;
            for (int j = t; j < blockIdx.x; j += CSR_THREADS) part += g_bsum[j];
            #pragma unroll
            for (int o = 16; o > 0; o >>= 1) part += __shfl_xor_sync(0xffffffffu, part, o);
            __syncthreads();                 // wsum free for reuse
            if (lane == 0) wsum[w] = part;
            __syncthreads();
            int base2 = 0;
            #pragma unroll
            for (int j = 0; j < 8; ++j) base2 += wsum[j];
            excl += base2;
        }
        // P4: write offsets (padded), fill pad slots with dummy node n
        int off = excl;
        for (int j = 0; j < C; ++j) {
            int idx = b0 + j;
            if (idx < n) {
                int d = g_deg[idx];
                int p = (d + 3) & ~3;
                g_off[idx] = off;
                g_cur[idx] = off;
                for (int k = d; k < p; ++k) g_csr[off + k] = n;  // dummy
                if (idx == n - 1) g_off[n] = off + p;
                off += p;
            }
        }
        gsync();
        // P5: scatter (2 chunks in flight)
        i = gt;
        for (; i + T < E4; i += 2 * T) {
            int4 sa = ((const int4*)src)[i];
            int4 da = ((const int4*)dst)[i];
            int4 sb = ((const int4*)src)[i + T];
            int4 db = ((const int4*)dst)[i + T];
            g_csr[atomicAdd(&g_cur[da.x], 1)] = sa.x;
            g_csr[atomicAdd(&g_cur[da.y], 1)] = sa.y;
            g_csr[atomicAdd(&g_cur[da.z], 1)] = sa.z;
            g_csr[atomicAdd(&g_cur[da.w], 1)] = sa.w;
            g_csr[atomicAdd(&g_cur[db.x], 1)] = sb.x;
            g_csr[atomicAdd(&g_cur[db.y], 1)] = sb.y;
            g_csr[atomicAdd(&g_cur[db.z], 1)] = sb.z;
            g_csr[atomicAdd(&g_cur[db.w], 1)] = sb.w;
        }
        if (i < E4) {
            int4 sa = ((const int4*)src)[i];
            int4 da = ((const int4*)dst)[i];
            g_csr[atomicAdd(&g_cur[da.x], 1)] = sa.x;
            g_csr[atomicAdd(&g_cur[da.y], 1)] = sa.y;
            g_csr[atomicAdd(&g_cur[da.z], 1)] = sa.z;
            g_csr[atomicAdd(&g_cur[da.w], 1)] = sa.w;
        }
        for (int e = E4 * 4 + gt; e < E; e += T) {
            g_csr[atomicAdd(&g_cur[dst[e]], 1)] = src[e];
        }
        return;
    }

    // -------------------- fold2 + proj1 path --------------------
    int pb = blockIdx.x - CSR_BLOCKS;
    if (pb == 0) {
        if (t < F1) {
            float s = 0.f, d = 0.f;
            for (int c = 0; c < OUTC; ++c) {
                float wv = W2[t * OUTC + c];
                s += wv * as2v[c];
                d += wv * ad2v[c];
            }
            g_was2[t] = s;
            g_wad2[t] = d;
            g_h1h[(size_t)n * F1 + t] = __float2half(0.f);
        }
        if (t < 2) { g_as1[2 * n + t] = -1e30f; g_ad1[2 * n + t] = 0.f; }
        if (t == 0) { g_as2[n] = -1e30f; g_ad2[n] = 0.f; }
        if (t < OUTC) g_h2h[(size_t)n * OUTC + t] = __float2half(0.f);
    }
    for (int i = t; i < IN_DIM * F1; i += 256) Ws[i] = W1[i];
    int base = pb * 32;
    #pragma unroll
    for (int i = 0; i < 4; ++i) {
        int idx = t + i * 256;
        int node = idx >> 5, k = idx & 31;
        int nn = base + node;
        xsT[k][node] = (nn < n) ? x[(size_t)nn * IN_DIM + k] : 0.f;
    }
    __syncthreads();
    int tx = t & 31;
    int ty = t >> 5;
    unsigned long long acc[4][2] = {};
    #pragma unroll
    for (int k = 0; k < IN_DIM; ++k) {
        ulonglong2 w = *(const ulonglong2*)&Ws[k * F1 + tx * 4];
        float4 xv = *(const float4*)&xsT[k][ty * 4];
        unsigned long long xp0 = packdup(xv.x), xp1 = packdup(xv.y);
        unsigned long long xp2 = packdup(xv.z), xp3 = packdup(xv.w);
        ffma2(acc[0][0], w.x, xp0); ffma2(acc[0][1], w.y, xp0);
        ffma2(acc[1][0], w.x, xp1); ffma2(acc[1][1], w.y, xp1);
        ffma2(acc[2][0], w.x, xp2); ffma2(acc[2][1], w.y, xp2);
        ffma2(acc[3][0], w.x, xp3); ffma2(acc[3][1], w.y, xp3);
    }
    float4 av = __ldg((const float4*)&attS[tx * 4]);
    float4 dvv = __ldg((const float4*)&attD[tx * 4]);
    #pragma unroll
    for (int i = 0; i < 4; ++i) {
        int nn = base + ty * 4 + i;
        float f0 = lo32(acc[i][0]), f1 = hi32(acc[i][0]);
        float f2 = lo32(acc[i][1]), f3 = hi32(acc[i][1]);
        if (nn < n) {
            __half2 p01 = __floats2half2_rn(f0, f1);
            __half2 p23 = __floats2half2_rn(f2, f3);
            uint2 u;
            u.x = reinterpret_cast<unsigned&>(p01);
            u.y = reinterpret_cast<unsigned&>(p23);
            *(uint2*)(g_h1h + (size_t)nn * F1 + tx * 4) = u;
        }
        float ps = f0 * av.x + f1 * av.y + f2 * av.z + f3 * av.w;
        float pd = f0 * dvv.x + f1 * dvv.y + f2 * dvv.z + f3 * dvv.w;
        #pragma unroll
        for (int o = 8; o > 0; o >>= 1) {
            ps += __shfl_xor_sync(0xffffffffu, ps, o);
            pd += __shfl_xor_sync(0xffffffffu, pd, o);
        }
        if ((tx & 15) == 0 && nn < n) {
            g_as1[2 * nn + (tx >> 4)] = ps * LOG2E;
            g_ad1[2 * nn + (tx >> 4)] = pd * LOG2E;
        }
    }
}

// ------- layer-1 gather: 2 nodes/warp, 16 lanes/node, 8 ch/lane ----------------
__global__ void __launch_bounds__(128)
k_gather1(const float* __restrict__ bias1,
          const float* __restrict__ gamma,
          const float* __restrict__ beta, int n) {
    int warp = (blockIdx.x * blockDim.x + threadIdx.x) >> 5;
    int lane = threadIdx.x & 31;
    int half = lane >> 4;
    int sub  = lane & 15;
    int node = warp * 2 + half;
    bool valid = node < n;
    if (warp * 2 >= n) return;
    int nd = valid ? node : n;
    int h = sub >> 3;
    float lad = g_ad1[2 * nd + h];
    float acc[8] = {}, accB[8] = {};
    float s = 0.f, sB = 0.f;
    // self-loop
    {
        float wv = exp2f(lrelu(g_as1[2 * nd + h] + lad));
        uint4 r = *(const uint4*)(g_h1h + (size_t)nd * F1 + sub * 8);
        float2 f;
        f = h2f2(r.x); acc[0] += wv * f.x; acc[1] += wv * f.y;
        f = h2f2(r.y); acc[2] += wv * f.x; acc[3] += wv * f.y;
        f = h2f2(r.z); acc[4] += wv * f.x; acc[5] += wv * f.y;
        f = h2f2(r.w); acc[6] += wv * f.x; acc[7] += wv * f.y;
        s += wv;
    }
    int e = 0, endp = 0;
    if (valid) { e = g_off[node]; endp = g_off[node + 1]; }
    for (; e < endp; e += 2) {
        int2 q = *(const int2*)&g_csr[e];
        float pA = g_as1[2 * q.x + h];
        float pB = g_as1[2 * q.y + h];
        uint4 rA = *(const uint4*)(g_h1h + (size_t)q.x * F1 + sub * 8);
        uint4 rB = *(const uint4*)(g_h1h + (size_t)q.y * F1 + sub * 8);
        float wA = exp2f(lrelu(pA + lad));
        float wB = exp2f(lrelu(pB + lad));
        float2 f;
        f = h2f2(rA.x); acc[0]  += wA * f.x; acc[1]  += wA * f.y;
        f = h2f2(rA.y); acc[2]  += wA * f.x; acc[3]  += wA * f.y;
        f = h2f2(rA.z); acc[4]  += wA * f.x; acc[5]  += wA * f.y;
        f = h2f2(rA.w); acc[6]  += wA * f.x; acc[7]  += wA * f.y;
        f = h2f2(rB.x); accB[0] += wB * f.x; accB[1] += wB * f.y;
        f = h2f2(rB.y); accB[2] += wB * f.x; accB[3] += wB * f.y;
        f = h2f2(rB.z); accB[4] += wB * f.x; accB[5] += wB * f.y;
        f = h2f2(rB.w); accB[6] += wB * f.x; accB[7] += wB * f.y;
        s += wA; sB += wB;
    }
    s += sB;
    float r = 1.f / s;
    int c = sub * 8;
    float4 bi0 = *(const float4*)&bias1[c];
    float4 bi1 = *(const float4*)&bias1[c + 4];
    float v[8];
    v[0] = (acc[0] + accB[0]) * r + bi0.x;
    v[1] = (acc[1] + accB[1]) * r + bi0.y;
    v[2] = (acc[2] + accB[2]) * r + bi0.z;
    v[3] = (acc[3] + accB[3]) * r + bi0.w;
    v[4] = (acc[4] + accB[4]) * r + bi1.x;
    v[5] = (acc[5] + accB[5]) * r + bi1.y;
    v[6] = (acc[6] + accB[6]) * r + bi1.z;
    v[7] = (acc[7] + accB[7]) * r + bi1.w;
    float tot = 0.f;
    #pragma unroll
    for (int i = 0; i < 8; ++i) tot += v[i];
    #pragma unroll
    for (int o = 8; o > 0; o >>= 1) tot += __shfl_xor_sync(0xffffffffu, tot, o);
    float mu = tot * (1.f / 128.f);
    float sq = 0.f;
    float dv[8];
    #pragma unroll
    for (int i = 0; i < 8; ++i) { dv[i] = v[i] - mu; sq += dv[i] * dv[i]; }
    #pragma unroll
    for (int o = 8; o > 0; o >>= 1) sq += __shfl_xor_sync(0xffffffffu, sq, o);
    float inv = rsqrtf(sq * (1.f / 128.f) + 1e-5f);
    float4 gm0 = *(const float4*)&gamma[c];
    float4 gm1 = *(const float4*)&gamma[c + 4];
    float4 bt0 = *(const float4*)&beta[c];
    float4 bt1 = *(const float4*)&beta[c + 4];
    float y[8];
    y[0] = fmaxf(dv[0] * inv * gm0.x + bt0.x, 0.f);
    y[1] = fmaxf(dv[1] * inv * gm0.y + bt0.y, 0.f);
    y[2] = fmaxf(dv[2] * inv * gm0.z + bt0.z, 0.f);
    y[3] = fmaxf(dv[3] * inv * gm0.w + bt0.w, 0.f);
    y[4] = fmaxf(dv[4] * inv * gm1.x + bt1.x, 0.f);
    y[5] = fmaxf(dv[5] * inv * gm1.y + bt1.y, 0.f);
    y[6] = fmaxf(dv[6] * inv * gm1.z + bt1.z, 0.f);
    y[7] = fmaxf(dv[7] * inv * gm1.w + bt1.w, 0.f);
    if (valid) {
        __half2 p0 = __floats2half2_rn(y[0], y[1]);
        __half2 p1 = __floats2half2_rn(y[2], y[3]);
        __half2 p2 = __floats2half2_rn(y[4], y[5]);
        __half2 p3 = __floats2half2_rn(y[6], y[7]);
        uint4 u;
        u.x = reinterpret_cast<unsigned&>(p0);
        u.y = reinterpret_cast<unsigned&>(p1);
        u.z = reinterpret_cast<unsigned&>(p2);
        u.w = reinterpret_cast<unsigned&>(p3);
        *(uint4*)(g_hlnh + (size_t)node * F1 + c) = u;
    }
    float4 ws0 = *(const float4*)&g_was2[c];
    float4 ws1 = *(const float4*)&g_was2[c + 4];
    float4 wd0 = *(const float4*)&g_wad2[c];
    float4 wd1 = *(const float4*)&g_wad2[c + 4];
    float sa = y[0] * ws0.x + y[1] * ws0.y + y[2] * ws0.z + y[3] * ws0.w
             + y[4] * ws1.x + y[5] * ws1.y + y[6] * ws1.z + y[7] * ws1.w;
    float sd = y[0] * wd0.x + y[1] * wd0.y + y[2] * wd0.z + y[3] * wd0.w
             + y[4] * wd1.x + y[5] * wd1.y + y[6] * wd1.z + y[7] * wd1.w;
    #pragma unroll
    for (int o = 8; o > 0; o >>= 1) {
        sa += __shfl_xor_sync(0xffffffffu, sa, o);
        sd += __shfl_xor_sync(0xffffffffu, sd, o);
    }
    if (sub == 0 && valid) { g_as2[node] = sa * LOG2E; g_ad2[node] = sd * LOG2E; }
}

// ---------------- layer-2 projection on TENSOR CORES (HMMA m16n8k16) -----------
__global__ void __launch_bounds__(256)
k4_proj(const float* __restrict__ W2, int n) {
    __shared__ __half W2T[OUTC][136];    // [n][k=0..127 + pad], 17408 B
    int t = threadIdx.x;
    for (int i = t; i < F1 * OUTC; i += 256) {
        int k = i >> 6, c = i & 63;
        W2T[c][k] = __float2half(W2[i]);
    }
    __syncthreads();
    int warp = t >> 5, lane = t & 31;
    int qr = lane >> 2;          // 0..7
    int qc = lane & 3;           // 0..3
    int node0 = blockIdx.x * 128 + warp * 16;
    int rowA = node0 + qr;
    int rowB = node0 + qr + 8;
    const __half* hA = g_hlnh + (size_t)min(rowA, n - 1) * F1;
    const __half* hB = g_hlnh + (size_t)min(rowB, n - 1) * F1;
    float cfr[8][4] = {};
    #pragma unroll
    for (int ks = 0; ks < 8; ++ks) {
        int k0 = ks * 16 + qc * 2;
        unsigned a0 = *(const unsigned*)(hA + k0);
        unsigned a1 = *(const unsigned*)(hB + k0);
        unsigned a2 = *(const unsigned*)(hA + k0 + 8);
        unsigned a3 = *(const unsigned*)(hB + k0 + 8);
        #pragma unroll
        for (int nt = 0; nt < 8; ++nt) {
            int bn = nt * 8 + qr;
            unsigned b0 = *(const unsigned*)&W2T[bn][k0];
            unsigned b1 = *(const unsigned*)&W2T[bn][k0 + 8];
            asm volatile(
                "mma.sync.aligned.m16n8k16.row.col.f32.f16.f16.f32 "
                "{%0,%1,%2,%3}, {%4,%5,%6,%7}, {%8,%9}, {%0,%1,%2,%3};"
                : "+f"(cfr[nt][0]), "+f"(cfr[nt][1]), "+f"(cfr[nt][2]), "+f"(cfr[nt][3])
                : "r"(a0), "r"(a1), "r"(a2), "r"(a3), "r"(b0), "r"(b1));
        }
    }
    bool vA = rowA < n, vB = rowB < n;
    __half* oA = g_h2h + (size_t)rowA * OUTC;
    __half* oB = g_h2h + (size_t)rowB * OUTC;
    #pragma unroll
    for (int nt = 0; nt < 8; ++nt) {
        int col = nt * 8 + qc * 2;
        if (vA) {
            __half2 p = __floats2half2_rn(cfr[nt][0], cfr[nt][1]);
            *(unsigned*)(oA + col) = reinterpret_cast<unsigned&>(p);
        }
        if (vB) {
            __half2 p = __floats2half2_rn(cfr[nt][2], cfr[nt][3]);
            *(unsigned*)(oB + col) = reinterpret_cast<unsigned&>(p);
        }
    }
}

// ------- layer-2 gather: 4 nodes/warp, 8 lanes/node, 8 ch/lane -----------------
// Tail duty: re-zero g_deg for the next kernel_launch call.
__global__ void __launch_bounds__(128)
k_gather2(float* __restrict__ out, const float* __restrict__ bias2, int n) {
    int gtid = blockIdx.x * blockDim.x + threadIdx.x;
    int warp = gtid >> 5;
    int lane = threadIdx.x & 31;
    int quad = lane >> 3;
    int sub  = lane & 7;
    int node = warp * 4 + quad;
    if (gtid < n) g_deg[gtid] = 0;
    bool valid = node < n;
    if (warp * 4 >= n) return;
    int nd = valid ? node : n;
    float lad = g_ad2[nd];
    float acc[8] = {}, accB[8] = {};
    float s = 0.f, sB = 0.f;
    {
        float wv = exp2f(lrelu(g_as2[nd] + lad));
        uint4 r = *(const uint4*)(g_h2h + (size_t)nd * OUTC + sub * 8);
        float2 f;
        f = h2f2(r.x); acc[0] += wv * f.x; acc[1] += wv * f.y;
        f = h2f2(r.y); acc[2] += wv * f.x; acc[3] += wv * f.y;
        f = h2f2(r.z); acc[4] += wv * f.x; acc[5] += wv * f.y;
        f = h2f2(r.w); acc[6] += wv * f.x; acc[7] += wv * f.y;
        s += wv;
    }
    int e = 0, endp = 0;
    if (valid) { e = g_off[node]; endp = g_off[node + 1]; }
    for (; e < endp; e += 2) {
        int2 q = *(const int2*)&g_csr[e];
        float pA = g_as2[q.x];
        float pB = g_as2[q.y];
        uint4 rA = *(const uint4*)(g_h2h + (size_t)q.x * OUTC + sub * 8);
        uint4 rB = *(const uint4*)(g_h2h + (size_t)q.y * OUTC + sub * 8);
        float wA = exp2f(lrelu(pA + lad));
        float wB = exp2f(lrelu(pB + lad));
        float2 f;
        f = h2f2(rA.x); acc[0]  += wA * f.x; acc[1]  += wA * f.y;
        f = h2f2(rA.y); acc[2]  += wA * f.x; acc[3]  += wA * f.y;
        f = h2f2(rA.z); acc[4]  += wA * f.x; acc[5]  += wA * f.y;
        f = h2f2(rA.w); acc[6]  += wA * f.x; acc[7]  += wA * f.y;
        f = h2f2(rB.x); accB[0] += wB * f.x; accB[1] += wB * f.y;
        f = h2f2(rB.y); accB[2] += wB * f.x; accB[3] += wB * f.y;
        f = h2f2(rB.z); accB[4] += wB * f.x; accB[5] += wB * f.y;
        f = h2f2(rB.w); accB[6] += wB * f.x; accB[7] += wB * f.y;
        s += wA; sB += wB;
    }
    s += sB;
    if (valid) {
        float r = 1.f / s;
        int c = sub * 8;
        float4 bi0 = *(const float4*)&bias2[c];
        float4 bi1 = *(const float4*)&bias2[c + 4];
        float4 o0, o1;
        o0.x = (acc[0] + accB[0]) * r + bi0.x;
        o0.y = (acc[1] + accB[1]) * r + bi0.y;
        o0.z = (acc[2] + accB[2]) * r + bi0.z;
        o0.w = (acc[3] + accB[3]) * r + bi0.w;
        o1.x = (acc[4] + accB[4]) * r + bi1.x;
        o1.y = (acc[5] + accB[5]) * r + bi1.y;
        o1.z = (acc[6] + accB[6]) * r + bi1.z;
        o1.w = (acc[7] + accB[7]) * r + bi1.w;
        *(float4*)(out + (size_t)node * OUTC + c)     = o0;
        *(float4*)(out + (size_t)node * OUTC + c + 4) = o1;
    }
}

// ---------------- launcher -----------------------------------------------------
extern "C" void kernel_launch(void* const* d_in, const int* in_sizes, int n_in,
                              void* d_out, int out_size) {
    const float* x     = (const float*)d_in[0];
    const int*   ei    = (const int*)  d_in[1];
    const float* W1    = (const float*)d_in[2];
    const float* as1   = (const float*)d_in[3];
    const float* ad1   = (const float*)d_in[4];
    const float* b1    = (const float*)d_in[5];
    const float* gamma = (const float*)d_in[6];
    const float* beta  = (const float*)d_in[7];
    const float* W2    = (const float*)d_in[8];
    const float* as2   = (const float*)d_in[9];
    const float* ad2   = (const float*)d_in[10];
    const float* b2    = (const float*)d_in[11];
    float* out = (float*)d_out;

    int n = in_sizes[0] / IN_DIM;
    int E = in_sizes[1] / 2;
    const int* srcp = ei;
    const int* dstp = ei + E;

    int proj_blocks = (n + 31) / 32;
    int g1_blocks = (((n + 1) / 2) + 3) / 4;     // 2 nodes/warp, 4 warps/block
    int g2_blocks = (((n + 3) / 4) + 3) / 4;     // 4 nodes/warp, 4 warps/block

    k_mega<<<CSR_BLOCKS + proj_blocks, 256>>>(srcp, dstp, E, n,
                                              x, W1, as1, ad1, W2, as2, ad2);  // 1
    k_gather1<<<g1_blocks, 128>>>(b1, gamma, beta, n);                         // 2
    k4_proj<<<(n + 127) / 128, 256>>>(W2, n);                                  // 3
    k_gather2<<<g2_blocks, 128>>>(out, b2, n);                                 // 4
}

// round 17
// speedup vs baseline: 1.0858x; 1.0187x over previous
#include <cuda_runtime.h>
#include <cuda_fp16.h>

#define N_NODES 100000
#define E_EDGES 1600000
#define IN_DIM 32
#define HID 64
#define NHEADS 2
#define F1 128   // NHEADS*HID
#define OUTC 64
#define LOG2E 1.4426950408889634f

#define CSR_BLOCKS 384
#define CSR_THREADS 256

// ---------------- scratch (device globals; no allocation allowed) ------------
__device__ __align__(16) __half g_h1h [(size_t)(N_NODES + 1) * F1];
__device__ __align__(16) __half g_hlnh[(size_t)N_NODES * F1];
__device__ __align__(16) __half g_h2h [(size_t)(N_NODES + 1) * OUTC];
__device__ __align__(16) float g_as1[(N_NODES + 1) * NHEADS];
__device__ __align__(16) float g_ad1[(N_NODES + 1) * NHEADS];
__device__ float g_as2[N_NODES + 1];
__device__ float g_ad2[N_NODES + 1];
__device__ int   g_deg[N_NODES];          // ZERO at kernel_launch entry (BSS init + tail-zeroed by k_gather2)
__device__ int   g_off[N_NODES + 1];
__device__ int   g_cur[N_NODES];
__device__ __align__(16) int g_csr[E_EDGES + 3 * N_NODES + 8];
__device__ int   g_bsum[CSR_BLOCKS];
__device__ int   g_bar_count;
__device__ int   g_bar_gen;
__device__ __align__(16) float g_was2[F1];
__device__ __align__(16) float g_wad2[F1];

__device__ __forceinline__ float lrelu(float v) { return v > 0.f ? v : 0.2f * v; }

// ---- packed fp32x2 helpers ----------------------------------------------------
__device__ __forceinline__ unsigned long long packdup(float a) {
    unsigned long long r;
    asm("mov.b64 %0, {%1, %1};" : "=l"(r) : "f"(a));
    return r;
}
__device__ __forceinline__ void ffma2(unsigned long long& acc,
                                      unsigned long long a, unsigned long long b) {
    asm("fma.rn.f32x2 %0, %1, %2, %0;" : "+l"(acc) : "l"(a), "l"(b));
}
__device__ __forceinline__ float lo32(unsigned long long v) {
    return __uint_as_float((unsigned)(v & 0xffffffffull));
}
__device__ __forceinline__ float hi32(unsigned long long v) {
    return __uint_as_float((unsigned)(v >> 32));
}
__device__ __forceinline__ float2 h2f2(unsigned h) {
    return __half22float2(reinterpret_cast<__half2&>(h));
}

// ---- software grid barrier (csr blocks only) -----------------------------------
__device__ __forceinline__ void gsync() {
    __syncthreads();
    __threadfence();
    if (threadIdx.x == 0) {
        int gen = *(volatile int*)&g_bar_gen;
        if (atomicAdd(&g_bar_count, 1) == CSR_BLOCKS - 1) {
            g_bar_count = 0;
            __threadfence();
            *(volatile int*)&g_bar_gen = gen + 1;
        } else {
            while (*(volatile int*)&g_bar_gen == gen) { }
        }
        __threadfence();
    }
    __syncthreads();
}

// ===== mega kernel: blocks [0,384) build CSR; blocks [384,...) do fold2+proj1 ===
// PRECONDITION: g_deg == 0 (BSS at load; re-zeroed by k_gather2 tail each call)
__global__ void __launch_bounds__(256, 4)
k_mega(const int* __restrict__ src, const int* __restrict__ dst, int E, int n,
       const float* __restrict__ x, const float* __restrict__ W1,
       const float* __restrict__ attS, const float* __restrict__ attD,
       const float* __restrict__ W2,
       const float* __restrict__ as2v, const float* __restrict__ ad2v) {
    __shared__ __align__(16) float Ws[IN_DIM * F1];      // proj: weights | csr: wsum alias
    __shared__ __align__(16) float xsT[IN_DIM][36];
    int t = threadIdx.x;

    if (blockIdx.x < CSR_BLOCKS) {
        // -------------------- CSR path --------------------
        int* wsum = (int*)xsT;
        const int T = CSR_BLOCKS * CSR_THREADS;
        int gt = blockIdx.x * CSR_THREADS + t;
        int lane = t & 31, w = t >> 5;

        // P1: count degrees (4 int4 chunks in flight)
        int E4 = E >> 2;
        int i = gt;
        for (; i + 3 * T < E4; i += 4 * T) {
            int4 a = ((const int4*)dst)[i];
            int4 b = ((const int4*)dst)[i + T];
            int4 c = ((const int4*)dst)[i + 2 * T];
            int4 d = ((const int4*)dst)[i + 3 * T];
            atomicAdd(&g_deg[a.x], 1); atomicAdd(&g_deg[a.y], 1);
            atomicAdd(&g_deg[a.z], 1); atomicAdd(&g_deg[a.w], 1);
            atomicAdd(&g_deg[b.x], 1); atomicAdd(&g_deg[b.y], 1);
            atomicAdd(&g_deg[b.z], 1); atomicAdd(&g_deg[b.w], 1);
            atomicAdd(&g_deg[c.x], 1); atomicAdd(&g_deg[c.y], 1);
            atomicAdd(&g_deg[c.z], 1); atomicAdd(&g_deg[c.w], 1);
            atomicAdd(&g_deg[d.x], 1); atomicAdd(&g_deg[d.y], 1);
            atomicAdd(&g_deg[d.z], 1); atomicAdd(&g_deg[d.w], 1);
        }
        for (; i < E4; i += T) {
            int4 a = ((const int4*)dst)[i];
            atomicAdd(&g_deg[a.x], 1); atomicAdd(&g_deg[a.y], 1);
            atomicAdd(&g_deg[a.z], 1); atomicAdd(&g_deg[a.w], 1);
        }
        for (int e = E4 * 4 + gt; e < E; e += T) atomicAdd(&g_deg[dst[e]], 1);
        gsync();
        // P2: per-thread chunk sum (padded to 4) + block scan -> g_bsum
        int C = (n + T - 1) / T;
        int b0 = gt * C;
        int s = 0;
        for (int j = 0; j < C; ++j) {
            int idx = b0 + j;
            if (idx < n) s += (g_deg[idx] + 3) & ~3;
        }
        int incl = s;
        #pragma unroll
        for (int o = 1; o < 32; o <<= 1) {
            int xv = __shfl_up_sync(0xffffffffu, incl, o);
            if (lane >= o) incl += xv;
        }
        if (lane == 31) wsum[w] = incl;
        __syncthreads();
        if (t < 8) {
            int xv = wsum[t];
            #pragma unroll
            for (int o = 1; o < 8; o <<= 1) {
                int y = __shfl_up_sync(0xffu, xv, o);
                if (t >= o) xv += y;
            }
            wsum[t] = xv;
        }
        __syncthreads();
        int excl = incl - s + (w > 0 ? wsum[w - 1] : 0);
        if (t == CSR_THREADS - 1) g_bsum[blockIdx.x] = excl + s;
        gsync();
        // P3 (barrier-free): every block reduces its own prefix of g_bsum
        {
            int part = 0;
            for (int j = t; j < blockIdx.x; j += CSR_THREADS) part += g_bsum[j];
            #pragma unroll
            for (int o = 16; o > 0; o >>= 1) part += __shfl_xor_sync(0xffffffffu, part, o);
            __syncthreads();                 // wsum free for reuse
            if (lane == 0) wsum[w] = part;
            __syncthreads();
            int base2 = 0;
            #pragma unroll
            for (int j = 0; j < 8; ++j) base2 += wsum[j];
            excl += base2;
        }
        // P4: write offsets (padded), fill pad slots with dummy node n
        int off = excl;
        for (int j = 0; j < C; ++j) {
            int idx = b0 + j;
            if (idx < n) {
                int d = g_deg[idx];
                int p = (d + 3) & ~3;
                g_off[idx] = off;
                g_cur[idx] = off;
                for (int k = d; k < p; ++k) g_csr[off + k] = n;  // dummy
                if (idx == n - 1) g_off[n] = off + p;
                off += p;
            }
        }
        gsync();
        // P5: scatter (4 chunks in flight)
        i = gt;
        for (; i + 3 * T < E4; i += 4 * T) {
            int4 sa = ((const int4*)src)[i];
            int4 da = ((const int4*)dst)[i];
            int4 sb = ((const int4*)src)[i + T];
            int4 db = ((const int4*)dst)[i + T];
            int4 sc = ((const int4*)src)[i + 2 * T];
            int4 dc = ((const int4*)dst)[i + 2 * T];
            int4 sd = ((const int4*)src)[i + 3 * T];
            int4 dd = ((const int4*)dst)[i + 3 * T];
            g_csr[atomicAdd(&g_cur[da.x], 1)] = sa.x;
            g_csr[atomicAdd(&g_cur[da.y], 1)] = sa.y;
            g_csr[atomicAdd(&g_cur[da.z], 1)] = sa.z;
            g_csr[atomicAdd(&g_cur[da.w], 1)] = sa.w;
            g_csr[atomicAdd(&g_cur[db.x], 1)] = sb.x;
            g_csr[atomicAdd(&g_cur[db.y], 1)] = sb.y;
            g_csr[atomicAdd(&g_cur[db.z], 1)] = sb.z;
            g_csr[atomicAdd(&g_cur[db.w], 1)] = sb.w;
            g_csr[atomicAdd(&g_cur[dc.x], 1)] = sc.x;
            g_csr[atomicAdd(&g_cur[dc.y], 1)] = sc.y;
            g_csr[atomicAdd(&g_cur[dc.z], 1)] = sc.z;
            g_csr[atomicAdd(&g_cur[dc.w], 1)] = sc.w;
            g_csr[atomicAdd(&g_cur[dd.x], 1)] = sd.x;
            g_csr[atomicAdd(&g_cur[dd.y], 1)] = sd.y;
            g_csr[atomicAdd(&g_cur[dd.z], 1)] = sd.z;
            g_csr[atomicAdd(&g_cur[dd.w], 1)] = sd.w;
        }
        for (; i < E4; i += T) {
            int4 sa = ((const int4*)src)[i];
            int4 da = ((const int4*)dst)[i];
            g_csr[atomicAdd(&g_cur[da.x], 1)] = sa.x;
            g_csr[atomicAdd(&g_cur[da.y], 1)] = sa.y;
            g_csr[atomicAdd(&g_cur[da.z], 1)] = sa.z;
            g_csr[atomicAdd(&g_cur[da.w], 1)] = sa.w;
        }
        for (int e = E4 * 4 + gt; e < E; e += T) {
            g_csr[atomicAdd(&g_cur[dst[e]], 1)] = src[e];
        }
        return;
    }

    // -------------------- fold2 + proj1 path --------------------
    int pb = blockIdx.x - CSR_BLOCKS;
    if (pb == 0) {
        if (t < F1) {
            float s = 0.f, d = 0.f;
            for (int c = 0; c < OUTC; ++c) {
                float wv = W2[t * OUTC + c];
                s += wv * as2v[c];
                d += wv * ad2v[c];
            }
            g_was2[t] = s;
            g_wad2[t] = d;
            g_h1h[(size_t)n * F1 + t] = __float2half(0.f);
        }
        if (t < 2) { g_as1[2 * n + t] = -1e30f; g_ad1[2 * n + t] = 0.f; }
        if (t == 0) { g_as2[n] = -1e30f; g_ad2[n] = 0.f; }
        if (t < OUTC) g_h2h[(size_t)n * OUTC + t] = __float2half(0.f);
    }
    for (int i = t; i < IN_DIM * F1; i += 256) Ws[i] = W1[i];
    int base = pb * 32;
    #pragma unroll
    for (int i = 0; i < 4; ++i) {
        int idx = t + i * 256;
        int node = idx >> 5, k = idx & 31;
        int nn = base + node;
        xsT[k][node] = (nn < n) ? x[(size_t)nn * IN_DIM + k] : 0.f;
    }
    __syncthreads();
    int tx = t & 31;
    int ty = t >> 5;
    unsigned long long acc[4][2] = {};
    #pragma unroll
    for (int k = 0; k < IN_DIM; ++k) {
        ulonglong2 w = *(const ulonglong2*)&Ws[k * F1 + tx * 4];
        float4 xv = *(const float4*)&xsT[k][ty * 4];
        unsigned long long xp0 = packdup(xv.x), xp1 = packdup(xv.y);
        unsigned long long xp2 = packdup(xv.z), xp3 = packdup(xv.w);
        ffma2(acc[0][0], w.x, xp0); ffma2(acc[0][1], w.y, xp0);
        ffma2(acc[1][0], w.x, xp1); ffma2(acc[1][1], w.y, xp1);
        ffma2(acc[2][0], w.x, xp2); ffma2(acc[2][1], w.y, xp2);
        ffma2(acc[3][0], w.x, xp3); ffma2(acc[3][1], w.y, xp3);
    }
    float4 av = __ldg((const float4*)&attS[tx * 4]);
    float4 dvv = __ldg((const float4*)&attD[tx * 4]);
    #pragma unroll
    for (int i = 0; i < 4; ++i) {
        int nn = base + ty * 4 + i;
        float f0 = lo32(acc[i][0]), f1 = hi32(acc[i][0]);
        float f2 = lo32(acc[i][1]), f3 = hi32(acc[i][1]);
        if (nn < n) {
            __half2 p01 = __floats2half2_rn(f0, f1);
            __half2 p23 = __floats2half2_rn(f2, f3);
            uint2 u;
            u.x = reinterpret_cast<unsigned&>(p01);
            u.y = reinterpret_cast<unsigned&>(p23);
            *(uint2*)(g_h1h + (size_t)nn * F1 + tx * 4) = u;
        }
        float ps = f0 * av.x + f1 * av.y + f2 * av.z + f3 * av.w;
        float pd = f0 * dvv.x + f1 * dvv.y + f2 * dvv.z + f3 * dvv.w;
        #pragma unroll
        for (int o = 8; o > 0; o >>= 1) {
            ps += __shfl_xor_sync(0xffffffffu, ps, o);
            pd += __shfl_xor_sync(0xffffffffu, pd, o);
        }
        if ((tx & 15) == 0 && nn < n) {
            g_as1[2 * nn + (tx >> 4)] = ps * LOG2E;
            g_ad1[2 * nn + (tx >> 4)] = pd * LOG2E;
        }
    }
}

// ------- layer-1 gather: 2 nodes/warp, 16 lanes/node, 8 ch/lane ----------------
__global__ void __launch_bounds__(128)
k_gather1(const float* __restrict__ bias1,
          const float* __restrict__ gamma,
          const float* __restrict__ beta, int n) {
    int warp = (blockIdx.x * blockDim.x + threadIdx.x) >> 5;
    int lane = threadIdx.x & 31;
    int half = lane >> 4;
    int sub  = lane & 15;
    int node = warp * 2 + half;
    bool valid = node < n;
    if (warp * 2 >= n) return;
    int nd = valid ? node : n;
    int h = sub >> 3;
    float lad = g_ad1[2 * nd + h];
    float acc[8] = {}, accB[8] = {};
    float s = 0.f, sB = 0.f;
    // self-loop
    {
        float wv = exp2f(lrelu(g_as1[2 * nd + h] + lad));
        uint4 r = *(const uint4*)(g_h1h + (size_t)nd * F1 + sub * 8);
        float2 f;
        f = h2f2(r.x); acc[0] += wv * f.x; acc[1] += wv * f.y;
        f = h2f2(r.y); acc[2] += wv * f.x; acc[3] += wv * f.y;
        f = h2f2(r.z); acc[4] += wv * f.x; acc[5] += wv * f.y;
        f = h2f2(r.w); acc[6] += wv * f.x; acc[7] += wv * f.y;
        s += wv;
    }
    int e = 0, endp = 0;
    if (valid) { e = g_off[node]; endp = g_off[node + 1]; }
    for (; e < endp; e += 2) {
        int2 q = *(const int2*)&g_csr[e];
        float pA = g_as1[2 * q.x + h];
        float pB = g_as1[2 * q.y + h];
        uint4 rA = *(const uint4*)(g_h1h + (size_t)q.x * F1 + sub * 8);
        uint4 rB = *(const uint4*)(g_h1h + (size_t)q.y * F1 + sub * 8);
        float wA = exp2f(lrelu(pA + lad));
        float wB = exp2f(lrelu(pB + lad));
        float2 f;
        f = h2f2(rA.x); acc[0]  += wA * f.x; acc[1]  += wA * f.y;
        f = h2f2(rA.y); acc[2]  += wA * f.x; acc[3]  += wA * f.y;
        f = h2f2(rA.z); acc[4]  += wA * f.x; acc[5]  += wA * f.y;
        f = h2f2(rA.w); acc[6]  += wA * f.x; acc[7]  += wA * f.y;
        f = h2f2(rB.x); accB[0] += wB * f.x; accB[1] += wB * f.y;
        f = h2f2(rB.y); accB[2] += wB * f.x; accB[3] += wB * f.y;
        f = h2f2(rB.z); accB[4] += wB * f.x; accB[5] += wB * f.y;
        f = h2f2(rB.w); accB[6] += wB * f.x; accB[7] += wB * f.y;
        s += wA; sB += wB;
    }
    s += sB;
    float r = 1.f / s;
    int c = sub * 8;
    float4 bi0 = *(const float4*)&bias1[c];
    float4 bi1 = *(const float4*)&bias1[c + 4];
    float v[8];
    v[0] = (acc[0] + accB[0]) * r + bi0.x;
    v[1] = (acc[1] + accB[1]) * r + bi0.y;
    v[2] = (acc[2] + accB[2]) * r + bi0.z;
    v[3] = (acc[3] + accB[3]) * r + bi0.w;
    v[4] = (acc[4] + accB[4]) * r + bi1.x;
    v[5] = (acc[5] + accB[5]) * r + bi1.y;
    v[6] = (acc[6] + accB[6]) * r + bi1.z;
    v[7] = (acc[7] + accB[7]) * r + bi1.w;
    float tot = 0.f;
    #pragma unroll
    for (int i = 0; i < 8; ++i) tot += v[i];
    #pragma unroll
    for (int o = 8; o > 0; o >>= 1) tot += __shfl_xor_sync(0xffffffffu, tot, o);
    float mu = tot * (1.f / 128.f);
    float sq = 0.f;
    float dv[8];
    #pragma unroll
    for (int i = 0; i < 8; ++i) { dv[i] = v[i] - mu; sq += dv[i] * dv[i]; }
    #pragma unroll
    for (int o = 8; o > 0; o >>= 1) sq += __shfl_xor_sync(0xffffffffu, sq, o);
    float inv = rsqrtf(sq * (1.f / 128.f) + 1e-5f);
    float4 gm0 = *(const float4*)&gamma[c];
    float4 gm1 = *(const float4*)&gamma[c + 4];
    float4 bt0 = *(const float4*)&beta[c];
    float4 bt1 = *(const float4*)&beta[c + 4];
    float y[8];
    y[0] = fmaxf(dv[0] * inv * gm0.x + bt0.x, 0.f);
    y[1] = fmaxf(dv[1] * inv * gm0.y + bt0.y, 0.f);
    y[2] = fmaxf(dv[2] * inv * gm0.z + bt0.z, 0.f);
    y[3] = fmaxf(dv[3] * inv * gm0.w + bt0.w, 0.f);
    y[4] = fmaxf(dv[4] * inv * gm1.x + bt1.x, 0.f);
    y[5] = fmaxf(dv[5] * inv * gm1.y + bt1.y, 0.f);
    y[6] = fmaxf(dv[6] * inv * gm1.z + bt1.z, 0.f);
    y[7] = fmaxf(dv[7] * inv * gm1.w + bt1.w, 0.f);
    if (valid) {
        __half2 p0 = __floats2half2_rn(y[0], y[1]);
        __half2 p1 = __floats2half2_rn(y[2], y[3]);
        __half2 p2 = __floats2half2_rn(y[4], y[5]);
        __half2 p3 = __floats2half2_rn(y[6], y[7]);
        uint4 u;
        u.x = reinterpret_cast<unsigned&>(p0);
        u.y = reinterpret_cast<unsigned&>(p1);
        u.z = reinterpret_cast<unsigned&>(p2);
        u.w = reinterpret_cast<unsigned&>(p3);
        *(uint4*)(g_hlnh + (size_t)node * F1 + c) = u;
    }
    float4 ws0 = *(const float4*)&g_was2[c];
    float4 ws1 = *(const float4*)&g_was2[c + 4];
    float4 wd0 = *(const float4*)&g_wad2[c];
    float4 wd1 = *(const float4*)&g_wad2[c + 4];
    float sa = y[0] * ws0.x + y[1] * ws0.y + y[2] * ws0.z + y[3] * ws0.w
             + y[4] * ws1.x + y[5] * ws1.y + y[6] * ws1.z + y[7] * ws1.w;
    float sd = y[0] * wd0.x + y[1] * wd0.y + y[2] * wd0.z + y[3] * wd0.w
             + y[4] * wd1.x + y[5] * wd1.y + y[6] * wd1.z + y[7] * wd1.w;
    #pragma unroll
    for (int o = 8; o > 0; o >>= 1) {
        sa += __shfl_xor_sync(0xffffffffu, sa, o);
        sd += __shfl_xor_sync(0xffffffffu, sd, o);
    }
    if (sub == 0 && valid) { g_as2[node] = sa * LOG2E; g_ad2[node] = sd * LOG2E; }
}

// ---------------- layer-2 projection on TENSOR CORES (HMMA m16n8k16) -----------
__global__ void __launch_bounds__(256)
k4_proj(const float* __restrict__ W2, int n) {
    __shared__ __half W2T[OUTC][136];    // [n][k=0..127 + pad], 17408 B
    int t = threadIdx.x;
    for (int i = t; i < F1 * OUTC; i += 256) {
        int k = i >> 6, c = i & 63;
        W2T[c][k] = __float2half(W2[i]);
    }
    __syncthreads();
    int warp = t >> 5, lane = t & 31;
    int qr = lane >> 2;          // 0..7
    int qc = lane & 3;           // 0..3
    int node0 = blockIdx.x * 128 + warp * 16;
    int rowA = node0 + qr;
    int rowB = node0 + qr + 8;
    const __half* hA = g_hlnh + (size_t)min(rowA, n - 1) * F1;
    const __half* hB = g_hlnh + (size_t)min(rowB, n - 1) * F1;
    float cfr[8][4] = {};
    #pragma unroll
    for (int ks = 0; ks < 8; ++ks) {
        int k0 = ks * 16 + qc * 2;
        unsigned a0 = *(const unsigned*)(hA + k0);
        unsigned a1 = *(const unsigned*)(hB + k0);
        unsigned a2 = *(const unsigned*)(hA + k0 + 8);
        unsigned a3 = *(const unsigned*)(hB + k0 + 8);
        #pragma unroll
        for (int nt = 0; nt < 8; ++nt) {
            int bn = nt * 8 + qr;
            unsigned b0 = *(const unsigned*)&W2T[bn][k0];
            unsigned b1 = *(const unsigned*)&W2T[bn][k0 + 8];
            asm volatile(
                "mma.sync.aligned.m16n8k16.row.col.f32.f16.f16.f32 "
                "{%0,%1,%2,%3}, {%4,%5,%6,%7}, {%8,%9}, {%0,%1,%2,%3};"
                : "+f"(cfr[nt][0]), "+f"(cfr[nt][1]), "+f"(cfr[nt][2]), "+f"(cfr[nt][3])
                : "r"(a0), "r"(a1), "r"(a2), "r"(a3), "r"(b0), "r"(b1));
        }
    }
    bool vA = rowA < n, vB = rowB < n;
    __half* oA = g_h2h + (size_t)rowA * OUTC;
    __half* oB = g_h2h + (size_t)rowB * OUTC;
    #pragma unroll
    for (int nt = 0; nt < 8; ++nt) {
        int col = nt * 8 + qc * 2;
        if (vA) {
            __half2 p = __floats2half2_rn(cfr[nt][0], cfr[nt][1]);
            *(unsigned*)(oA + col) = reinterpret_cast<unsigned&>(p);
        }
        if (vB) {
            __half2 p = __floats2half2_rn(cfr[nt][2], cfr[nt][3]);
            *(unsigned*)(oB + col) = reinterpret_cast<unsigned&>(p);
        }
    }
}

// ------- layer-2 gather: 4 nodes/warp, 8 lanes/node, 8 ch/lane -----------------
// Tail duty: re-zero g_deg for the next kernel_launch call.
__global__ void __launch_bounds__(128)
k_gather2(float* __restrict__ out, const float* __restrict__ bias2, int n) {
    int gtid = blockIdx.x * blockDim.x + threadIdx.x;
    int warp = gtid >> 5;
    int lane = threadIdx.x & 31;
    int quad = lane >> 3;
    int sub  = lane & 7;
    int node = warp * 4 + quad;
    if (gtid < n) g_deg[gtid] = 0;
    bool valid = node < n;
    if (warp * 4 >= n) return;
    int nd = valid ? node : n;
    float lad = g_ad2[nd];
    float acc[8] = {}, accB[8] = {};
    float s = 0.f, sB = 0.f;
    {
        float wv = exp2f(lrelu(g_as2[nd] + lad));
        uint4 r = *(const uint4*)(g_h2h + (size_t)nd * OUTC + sub * 8);
        float2 f;
        f = h2f2(r.x); acc[0] += wv * f.x; acc[1] += wv * f.y;
        f = h2f2(r.y); acc[2] += wv * f.x; acc[3] += wv * f.y;
        f = h2f2(r.z); acc[4] += wv * f.x; acc[5] += wv * f.y;
        f = h2f2(r.w); acc[6] += wv * f.x; acc[7] += wv * f.y;
        s += wv;
    }
    int e = 0, endp = 0;
    if (valid) { e = g_off[node]; endp = g_off[node + 1]; }
    for (; e < endp; e += 2) {
        int2 q = *(const int2*)&g_csr[e];
        float pA = g_as2[q.x];
        float pB = g_as2[q.y];
        uint4 rA = *(const uint4*)(g_h2h + (size_t)q.x * OUTC + sub * 8);
        uint4 rB = *(const uint4*)(g_h2h + (size_t)q.y * OUTC + sub * 8);
        float wA = exp2f(lrelu(pA + lad));
        float wB = exp2f(lrelu(pB + lad));
        float2 f;
        f = h2f2(rA.x); acc[0]  += wA * f.x; acc[1]  += wA * f.y;
        f = h2f2(rA.y); acc[2]  += wA * f.x; acc[3]  += wA * f.y;
        f = h2f2(rA.z); acc[4]  += wA * f.x; acc[5]  += wA * f.y;
        f = h2f2(rA.w); acc[6]  += wA * f.x; acc[7]  += wA * f.y;
        f = h2f2(rB.x); accB[0] += wB * f.x; accB[1] += wB * f.y;
        f = h2f2(rB.y); accB[2] += wB * f.x; accB[3] += wB * f.y;
        f = h2f2(rB.z); accB[4] += wB * f.x; accB[5] += wB * f.y;
        f = h2f2(rB.w); accB[6] += wB * f.x; accB[7] += wB * f.y;
        s += wA; sB += wB;
    }
    s += sB;
    if (valid) {
        float r = 1.f / s;
        int c = sub * 8;
        float4 bi0 = *(const float4*)&bias2[c];
        float4 bi1 = *(const float4*)&bias2[c + 4];
        float4 o0, o1;
        o0.x = (acc[0] + accB[0]) * r + bi0.x;
        o0.y = (acc[1] + accB[1]) * r + bi0.y;
        o0.z = (acc[2] + accB[2]) * r + bi0.z;
        o0.w = (acc[3] + accB[3]) * r + bi0.w;
        o1.x = (acc[4] + accB[4]) * r + bi1.x;
        o1.y = (acc[5] + accB[5]) * r + bi1.y;
        o1.z = (acc[6] + accB[6]) * r + bi1.z;
        o1.w = (acc[7] + accB[7]) * r + bi1.w;
        *(float4*)(out + (size_t)node * OUTC + c)     = o0;
        *(float4*)(out + (size_t)node * OUTC + c + 4) = o1;
    }
}

// ---------------- launcher -----------------------------------------------------
extern "C" void kernel_launch(void* const* d_in, const int* in_sizes, int n_in,
                              void* d_out, int out_size) {
    const float* x     = (const float*)d_in[0];
    const int*   ei    = (const int*)  d_in[1];
    const float* W1    = (const float*)d_in[2];
    const float* as1   = (const float*)d_in[3];
    const float* ad1   = (const float*)d_in[4];
    const float* b1    = (const float*)d_in[5];
    const float* gamma = (const float*)d_in[6];
    const float* beta  = (const float*)d_in[7];
    const float* W2    = (const float*)d_in[8];
    const float* as2   = (const float*)d_in[9];
    const float* ad2   = (const float*)d_in[10];
    const float* b2    = (const float*)d_in[11];
    float* out = (float*)d_out;

    int n = in_sizes[0] / IN_DIM;
    int E = in_sizes[1] / 2;
    const int* srcp = ei;
    const int* dstp = ei + E;

    int proj_blocks = (n + 31) / 32;
    int g1_blocks = (((n + 1) / 2) + 3) / 4;     // 2 nodes/warp, 4 warps/block
    int g2_blocks = (((n + 3) / 4) + 3) / 4;     // 4 nodes/warp, 4 warps/block

    k_mega<<<CSR_BLOCKS + proj_blocks, 256>>>(srcp, dstp, E, n,
                                              x, W1, as1, ad1, W2, as2, ad2);  // 1
    k_gather1<<<g1_blocks, 128>>>(b1, gamma, beta, n);                         // 2
    k4_proj<<<(n + 127) / 128, 256>>>(W2, n);                                  // 3
    k_gather2<<<g2_blocks, 128>>>(out, b2, n);                                 // 4
}